// round 5
// baseline (speedup 1.0000x reference)
#include <cuda_runtime.h>

#define BATCH 4096
#define SEQL  200
#define NT    500
#define OBS   2
#define LAT   4
#define RNN   25
#define ODEH  20

// Output layout: x_pred [T,B,OBS] | z_traj [T,B,LAT] | z0 [B,LAT] | mu [B,LAT] | logvar [B,LAT]
#define XP_OFF 0
#define ZT_OFF (NT * BATCH * OBS)
#define Z0_OFF (ZT_OFF + NT * BATCH * LAT)
#define MU_OFF (Z0_OFF + BATCH * LAT)
#define LV_OFF (MU_OFF + BATCH * LAT)

typedef unsigned long long ULL;

// scratch: GI[b][l][75] = tanh(obs@encW+encB) @ Wih + bih   (245.76 MB)
__device__ float g_gi[(size_t)BATCH * SEQL * 75];

// ---------- f32x2 packed helpers ----------
__device__ __forceinline__ ULL pack2(float lo, float hi) {
    ULL r; asm("mov.b64 %0, {%1, %2};" : "=l"(r) : "f"(lo), "f"(hi)); return r;
}
__device__ __forceinline__ float2 unpack2(ULL v) {
    float2 r; asm("mov.b64 {%0, %1}, %2;" : "=f"(r.x), "=f"(r.y) : "l"(v)); return r;
}
__device__ __forceinline__ ULL fma2(ULL a, ULL b, ULL c) {
    ULL d; asm("fma.rn.f32x2 %0, %1, %2, %3;" : "=l"(d) : "l"(a), "l"(b), "l"(c)); return d;
}

// ---------- fast transcendentals (exp-based, ~1e-6 rel) ----------
__device__ __forceinline__ float sig_fast(float x) {
    return __fdividef(1.0f, 1.0f + __expf(-x));
}
__device__ __forceinline__ float tanh_fast(float x) {
    float ax = fabsf(x);
    float e  = __expf(-2.0f * ax);
    float t  = __fdividef(1.0f - e, 1.0f + e);
    return copysignf(t, x);
}
__device__ __forceinline__ float elu_fast(float x) {
    float m = fminf(x, 0.0f);
    float e = __expf(m) - 1.0f;
    return e + (x - m);
}

// =====================================================================================
// Kernel 0: GI precompute. Thread handles rows rowA and rowA+HALF (shared weight LDS).
// GI[row][j] = (tanh(obs@encW+encB) @ Wih + bih)[j], row = b*SEQL + l.
// =====================================================================================
__global__ void __launch_bounds__(128) gi_kernel(
    const float* __restrict__ obs,
    const float* __restrict__ encW, const float* __restrict__ encB,
    const float* __restrict__ Wih,  const float* __restrict__ bih)
{
    __shared__ ULL   sW[25 * 38];
    __shared__ ULL   sB[38];
    __shared__ float sE[75];
    __shared__ float st[4][32 * 76];

    const int tid = threadIdx.x;
    for (int idx = tid; idx < 25 * 38; idx += 128) {
        const int k = idx / 38, p = idx - k * 38;
        const int j0 = 2 * p, j1 = j0 + 1;
        const float w0 = Wih[k * 75 + j0];
        const float w1 = (j1 < 75) ? Wih[k * 75 + j1] : 0.f;
        sW[idx] = pack2(w0, w1);
    }
    if (tid < 38) {
        const int j0 = 2 * tid, j1 = j0 + 1;
        sB[tid] = pack2(bih[j0], (j1 < 75) ? bih[j1] : 0.f);
    }
    if (tid < 25) { sE[tid] = encW[tid]; sE[25 + tid] = encW[25 + tid]; sE[50 + tid] = encB[tid]; }
    __syncthreads();

    const int wid = tid >> 5, lane = tid & 31;
    const int HALF = BATCH * SEQL / 2;                // 409600
    const int rowA = blockIdx.x * 128 + tid;
    const int rowB = rowA + HALF;

    const float2 oA = ((const float2*)obs)[rowA];
    const float2 oB = ((const float2*)obs)[rowB];

    ULL accA[38], accB[38];
    #pragma unroll
    for (int p = 0; p < 38; p++) { accA[p] = sB[p]; accB[p] = sB[p]; }

    #pragma unroll 1
    for (int k = 0; k < 25; k++) {
        const float e0 = sE[k], e1 = sE[25 + k], eb = sE[50 + k];
        const float xA = tanh_fast(fmaf(oA.y, e1, fmaf(oA.x, e0, eb)));
        const float xB = tanh_fast(fmaf(oB.y, e1, fmaf(oB.x, e0, eb)));
        const ULL xA2 = pack2(xA, xA);
        const ULL xB2 = pack2(xB, xB);
        const ULL* wr = sW + k * 38;
        #pragma unroll
        for (int p = 0; p < 38; p++) {
            const ULL w = wr[p];
            accA[p] = fma2(xA2, w, accA[p]);
            accB[p] = fma2(xB2, w, accB[p]);
        }
    }

    float* s = st[wid];
    // phase A: stage + coalesced write
    #pragma unroll
    for (int p = 0; p < 38; p++) {
        const float2 v = unpack2(accA[p]);
        s[lane * 76 + 2 * p] = v.x; s[lane * 76 + 2 * p + 1] = v.y;
    }
    __syncwarp();
    {
        const size_t base = ((size_t)(blockIdx.x * 128 + wid * 32)) * 75;
        #pragma unroll 4
        for (int r = 0; r < 32; r++)
            for (int c = lane; c < 75; c += 32) g_gi[base + r * 75 + c] = s[r * 76 + c];
    }
    __syncwarp();
    // phase B
    #pragma unroll
    for (int p = 0; p < 38; p++) {
        const float2 v = unpack2(accB[p]);
        s[lane * 76 + 2 * p] = v.x; s[lane * 76 + 2 * p + 1] = v.y;
    }
    __syncwarp();
    {
        const size_t base = ((size_t)(blockIdx.x * 128 + wid * 32) + HALF) * 75;
        #pragma unroll 4
        for (int r = 0; r < 32; r++)
            for (int c = lane; c < 75; c += 32) g_gi[base + r * 75 + c] = s[r * 76 + c];
    }
}

// =====================================================================================
// Kernel 1: reverse GRU recurrence, h-side only (x-side streamed from GI, prefetch-2).
// One warp per element; lane i owns gate column i.
// =====================================================================================
__global__ void __launch_bounds__(128, 3) gru_kernel(
    const float* __restrict__ Whh, const float* __restrict__ bhh,
    const float* __restrict__ stW, const float* __restrict__ stB,
    float* __restrict__ out)
{
    __shared__ __align__(16) float shh[4][28];

    const int wid  = threadIdx.x >> 5;
    const int lane = threadIdx.x & 31;
    const int b    = blockIdx.x * 4 + wid;
    const int i    = (lane < RNN) ? lane : (RNN - 1);

    ULL whr[14], whz[14], whn[14];
    #pragma unroll
    for (int p = 0; p < 14; p++) {
        const int k0 = 2 * p, k1 = k0 + 1;
        const float r0 = (k0 < RNN) ? Whh[k0 * 75 + i]      : 0.f;
        const float r1 = (k1 < RNN) ? Whh[k1 * 75 + i]      : 0.f;
        const float z0 = (k0 < RNN) ? Whh[k0 * 75 + i + 25] : 0.f;
        const float z1 = (k1 < RNN) ? Whh[k1 * 75 + i + 25] : 0.f;
        const float n0 = (k0 < RNN) ? Whh[k0 * 75 + i + 50] : 0.f;
        const float n1 = (k1 < RNN) ? Whh[k1 * 75 + i + 50] : 0.f;
        whr[p] = pack2(r0, r1); whz[p] = pack2(z0, z1); whn[p] = pack2(n0, n1);
    }
    const float chr = bhh[i], chz = bhh[25 + i], chn = bhh[50 + i];

    if (lane < 28) shh[wid][lane] = 0.f;
    __syncwarp();

    float h = 0.f;
    const float* gb = g_gi + (size_t)b * SEQL * 75 + i;
    // prefetch depth 2
    float c0 = gb[199 * 75], c1 = gb[199 * 75 + 25], c2 = gb[199 * 75 + 50];
    float n0 = gb[198 * 75], n1 = gb[198 * 75 + 25], n2 = gb[198 * 75 + 50];

    const ulonglong2* h4 = (const ulonglong2*)shh[wid];

    for (int l = SEQL - 1; l >= 0; --l) {
        float p0 = 0.f, p1 = 0.f, p2 = 0.f;
        if (l >= 2) {
            const float* gq = gb + (l - 2) * 75;
            p0 = gq[0]; p1 = gq[25]; p2 = gq[50];
        }

        ULL Ra = 0, Rb = 0, Za = 0, Zb = 0, Na = 0, Nb = 0;
        #pragma unroll
        for (int q = 0; q < 7; q++) {
            const ulonglong2 hv = h4[q];
            Ra = fma2(hv.x, whr[2 * q], Ra);  Rb = fma2(hv.y, whr[2 * q + 1], Rb);
            Za = fma2(hv.x, whz[2 * q], Za);  Zb = fma2(hv.y, whz[2 * q + 1], Zb);
            Na = fma2(hv.x, whn[2 * q], Na);  Nb = fma2(hv.y, whn[2 * q + 1], Nb);
        }
        const float2 ra = unpack2(Ra), rb = unpack2(Rb);
        const float2 za = unpack2(Za), zb = unpack2(Zb);
        const float2 na = unpack2(Na), nb = unpack2(Nb);
        const float ghr = (ra.x + ra.y) + (rb.x + rb.y);
        const float ghz = (za.x + za.y) + (zb.x + zb.y);
        const float ghn = (na.x + na.y) + (nb.x + nb.y);

        const float r  = sig_fast(c0 + chr + ghr);
        const float zg = sig_fast(c1 + chz + ghz);
        const float n  = tanh_fast(fmaf(r, chn + ghn, c2));

        __syncwarp();                          // all lanes done reading old h
        h = fmaf(zg, h - n, n);
        if (lane < RNN) shh[wid][lane] = h;
        __syncwarp();

        c0 = n0; c1 = n1; c2 = n2;
        n0 = p0; n1 = p1; n2 = p2;
    }

    if (lane < 8) {
        float s = stB[lane];
        #pragma unroll
        for (int k = 0; k < RNN; k++) s = fmaf(shh[wid][k], stW[k * 8 + lane], s);
        if (lane < 4) {
            out[Z0_OFF + b * 4 + lane] = s;
            out[MU_OFF + b * 4 + lane] = s;
        } else {
            out[LV_OFF + b * 4 + (lane - 4)] = s;
        }
    }
}

// =====================================================================================
// Kernel 2: dopri5 + FSAL + cubic-Hermite dense output (8 intervals per big step)
// + fused decoder. 4 lanes/element; lane g owns outputs o=g and o=g+4 of each group.
// =====================================================================================
__device__ __forceinline__ void feval(
    const float (&y)[LAT], float (&k)[LAT],
    const float (&w1)[LAT][5], const float (&b1v)[5],
    const float (&w2)[5][LAT], const float (&b2v)[LAT])
{
    float v[5];
    #pragma unroll
    for (int u = 0; u < 5; u++) {
        float t = b1v[u];
        #pragma unroll
        for (int c = 0; c < LAT; c++) t = fmaf(y[c], w1[c][u], t);
        v[u] = elu_fast(t);
    }
    #pragma unroll
    for (int i = 0; i < LAT; i++) {
        float a  = fmaf(v[0], w2[0][i], v[1] * w2[1][i]);
        float bq = fmaf(v[2], w2[2][i], v[3] * w2[3][i]);
        float s  = fmaf(v[4], w2[4][i], a + bq);
        s += __shfl_xor_sync(0xffffffffu, s, 1);
        s += __shfl_xor_sync(0xffffffffu, s, 2);
        k[i] = s + b2v[i];
    }
}

__device__ __forceinline__ void decode_store(
    const float (&zg)[LAT],
    const float4* __restrict__ sW1, const float2* __restrict__ sW2,
    const float*  __restrict__ sb1, float b20, float b21,
    float* __restrict__ out, int tt, int b)
{
    float x0 = b20, x1 = b21;
    #pragma unroll
    for (int u = 0; u < ODEH; u++) {
        const float4 wv = sW1[u];
        float t = sb1[u];
        t = fmaf(zg[0], wv.x, t);
        t = fmaf(zg[1], wv.y, t);
        t = fmaf(zg[2], wv.z, t);
        t = fmaf(zg[3], wv.w, t);
        t = fmaxf(t, 0.0f);
        const float2 w2v = sW2[u];
        x0 = fmaf(t, w2v.x, x0);
        x1 = fmaf(t, w2v.y, x1);
    }
    float2 ov = {x0, x1};
    *(float2*)(out + XP_OFF + ((size_t)tt * BATCH + b) * 2) = ov;
}

__global__ void __launch_bounds__(128) ode_kernel(
    const float* __restrict__ pt,
    const float* __restrict__ W1,  const float* __restrict__ B1,
    const float* __restrict__ W2,  const float* __restrict__ B2,
    const float* __restrict__ dW1, const float* __restrict__ dB1,
    const float* __restrict__ dW2, const float* __restrict__ dB2,
    float* __restrict__ out)
{
    __shared__ float  spt[NT];
    __shared__ float4 sW1[ODEH];
    __shared__ float2 sW2[ODEH];
    __shared__ float  sb1[ODEH];

    const int tid = threadIdx.x;
    for (int idx = tid; idx < NT; idx += 128) spt[idx] = pt[idx];
    if (tid < ODEH) {
        sW1[tid] = make_float4(dW1[tid], dW1[ODEH + tid], dW1[2 * ODEH + tid], dW1[3 * ODEH + tid]);
        sW2[tid] = make_float2(dW2[tid * 2], dW2[tid * 2 + 1]);
        sb1[tid] = dB1[tid];
    }
    __syncthreads();

    const int gtid = blockIdx.x * 128 + tid;
    const int b    = gtid >> 2;
    const int g    = gtid & 3;
    const float b20 = dB2[0], b21 = dB2[1];

    float w1[LAT][5], b1v[5], w2[5][LAT], b2v[LAT];
    #pragma unroll
    for (int u = 0; u < 5; u++) {
        const int j = g * 5 + u;
        b1v[u] = B1[j];
        #pragma unroll
        for (int c = 0; c < LAT; c++) w1[c][u] = W1[c * ODEH + j];
        #pragma unroll
        for (int i = 0; i < LAT; i++) w2[u][i] = W2[j * LAT + i];
    }
    #pragma unroll
    for (int i = 0; i < LAT; i++) b2v[i] = B2[i];

    const float4 z0v = *(const float4*)(out + Z0_OFF + (size_t)b * 4);
    float z[LAT] = {z0v.x, z0v.y, z0v.z, z0v.w};
    if (g == 0) {
        *(float4*)(out + ZT_OFF + (size_t)b * 4) = z0v;
        decode_store(z, sW1, sW2, sb1, b20, b21, out, 0, b);
    }

    const float A21 = 0.2f;
    const float A31 = 3.0f/40.0f,       A32 = 9.0f/40.0f;
    const float A41 = 44.0f/45.0f,      A42 = -56.0f/15.0f,      A43 = 32.0f/9.0f;
    const float A51 = 19372.0f/6561.0f, A52 = -25360.0f/2187.0f, A53 = 64448.0f/6561.0f, A54 = -212.0f/729.0f;
    const float A61 = 9017.0f/3168.0f,  A62 = -355.0f/33.0f,     A63 = 46732.0f/5247.0f,
                A64 = 49.0f/176.0f,     A65 = -5103.0f/18656.0f;
    const float BB1 = 35.0f/384.0f,     BB3 = 500.0f/1113.0f,    BB4 = 125.0f/192.0f,
                BB5 = -2187.0f/6784.0f, BB6 = 11.0f/84.0f;

    float k1[LAT], k2[LAT], k3[LAT], k4[LAT], k5[LAT], k6[LAT], k7[LAT], y[LAT], z1[LAT];

    feval(z, k1, w1, b1v, w2, b2v);   // initial (FSAL thereafter)

    int m = 0;
    #pragma unroll 1
    for (int grp = 0; grp < 63; ++grp) {
        const int n = (grp < 62) ? 8 : 3;          // 499 = 62*8 + 3
        const float pt0 = spt[m];
        const float h   = spt[m + n] - pt0;

        #pragma unroll
        for (int i = 0; i < LAT; i++) y[i] = fmaf(h, A21 * k1[i], z[i]);
        feval(y, k2, w1, b1v, w2, b2v);
        #pragma unroll
        for (int i = 0; i < LAT; i++) {
            float s = fmaf(A32, k2[i], A31 * k1[i]);
            y[i] = fmaf(h, s, z[i]);
        }
        feval(y, k3, w1, b1v, w2, b2v);
        #pragma unroll
        for (int i = 0; i < LAT; i++) {
            float s = fmaf(A43, k3[i], fmaf(A42, k2[i], A41 * k1[i]));
            y[i] = fmaf(h, s, z[i]);
        }
        feval(y, k4, w1, b1v, w2, b2v);
        #pragma unroll
        for (int i = 0; i < LAT; i++) {
            float s = fmaf(A54, k4[i], fmaf(A53, k3[i], fmaf(A52, k2[i], A51 * k1[i])));
            y[i] = fmaf(h, s, z[i]);
        }
        feval(y, k5, w1, b1v, w2, b2v);
        #pragma unroll
        for (int i = 0; i < LAT; i++) {
            float s = fmaf(A65, k5[i], fmaf(A64, k4[i], fmaf(A63, k3[i], fmaf(A62, k2[i], A61 * k1[i]))));
            y[i] = fmaf(h, s, z[i]);
        }
        feval(y, k6, w1, b1v, w2, b2v);
        #pragma unroll
        for (int i = 0; i < LAT; i++) {
            float s = fmaf(BB6, k6[i], fmaf(BB5, k5[i], fmaf(BB4, k4[i], fmaf(BB3, k3[i], BB1 * k1[i]))));
            z1[i] = fmaf(h, s, z[i]);
        }
        feval(z1, k7, w1, b1v, w2, b2v);  // FSAL: k7 = f(z1) = next k1

        // lane g handles outputs o = g and o = g+4 (o < n); o == n-1 uses exact z1
        #pragma unroll
        for (int half = 0; half < 2; half++) {
            const int o = g + half * 4;
            if (o < n) {
                const int tt = m + 1 + o;
                float zg[LAT];
                if (o == n - 1) {
                    #pragma unroll
                    for (int i = 0; i < LAT; i++) zg[i] = z1[i];
                } else {
                    const float s  = __fdividef(spt[tt] - pt0, h);
                    const float s2 = s * s;
                    const float s3 = s2 * s;
                    const float c0 = 2.0f * s3 - 3.0f * s2 + 1.0f;
                    const float c1 = (s3 - 2.0f * s2 + s) * h;
                    const float c2 = 3.0f * s2 - 2.0f * s3;
                    const float c3 = (s3 - s2) * h;
                    #pragma unroll
                    for (int i = 0; i < LAT; i++)
                        zg[i] = fmaf(c3, k7[i], fmaf(c2, z1[i], fmaf(c1, k1[i], c0 * z[i])));
                }
                float4 zo = {zg[0], zg[1], zg[2], zg[3]};
                *(float4*)(out + ZT_OFF + ((size_t)tt * BATCH + b) * 4) = zo;
                decode_store(zg, sW1, sW2, sb1, b20, b21, out, tt, b);
            }
        }

        #pragma unroll
        for (int i = 0; i < LAT; i++) { z[i] = z1[i]; k1[i] = k7[i]; }
        m += n;
    }
}

// =====================================================================================
extern "C" void kernel_launch(void* const* d_in, const int* in_sizes, int n_in,
                              void* d_out, int out_size)
{
    const float* obs   = (const float*)d_in[0];
    const float* pt    = (const float*)d_in[1];
    const float* encW  = (const float*)d_in[2];
    const float* encB  = (const float*)d_in[3];
    const float* Wih   = (const float*)d_in[4];
    const float* Whh   = (const float*)d_in[5];
    const float* bih   = (const float*)d_in[6];
    const float* bhh   = (const float*)d_in[7];
    const float* stW   = (const float*)d_in[8];
    const float* stB   = (const float*)d_in[9];
    const float* oW1   = (const float*)d_in[10];
    const float* ob1   = (const float*)d_in[11];
    const float* oW2   = (const float*)d_in[12];
    const float* ob2   = (const float*)d_in[13];
    const float* dW1   = (const float*)d_in[14];
    const float* db1   = (const float*)d_in[15];
    const float* dW2   = (const float*)d_in[16];
    const float* db2   = (const float*)d_in[17];
    float* out = (float*)d_out;

    gi_kernel<<<BATCH * SEQL / 256, 128>>>(obs, encW, encB, Wih, bih);
    gru_kernel<<<BATCH / 4, 128>>>(Whh, bhh, stW, stB, out);
    ode_kernel<<<(BATCH * 4) / 128, 128>>>(pt, oW1, ob1, oW2, ob2, dW1, db1, dW2, db2, out);
}

// round 6
// speedup vs baseline: 1.1860x; 1.1860x over previous
#include <cuda_runtime.h>

#define BATCH 4096
#define SEQL  200
#define NT    500
#define OBS   2
#define LAT   4
#define RNN   25
#define ODEH  20

// Output layout: x_pred [T,B,OBS] | z_traj [T,B,LAT] | z0 [B,LAT] | mu [B,LAT] | logvar [B,LAT]
#define XP_OFF 0
#define ZT_OFF (NT * BATCH * OBS)
#define Z0_OFF (ZT_OFF + NT * BATCH * LAT)
#define MU_OFF (Z0_OFF + BATCH * LAT)
#define LV_OFF (MU_OFF + BATCH * LAT)

typedef unsigned long long ULL;

// scratch: GI[b][l][75] = tanh(obs@encW+encB) @ Wih + bih   (245.76 MB)
__device__ float g_gi[(size_t)BATCH * SEQL * 75];

// ---------- f32x2 packed helpers ----------
__device__ __forceinline__ ULL pack2(float lo, float hi) {
    ULL r; asm("mov.b64 %0, {%1, %2};" : "=l"(r) : "f"(lo), "f"(hi)); return r;
}
__device__ __forceinline__ float2 unpack2(ULL v) {
    float2 r; asm("mov.b64 {%0, %1}, %2;" : "=f"(r.x), "=f"(r.y) : "l"(v)); return r;
}
__device__ __forceinline__ ULL fma2(ULL a, ULL b, ULL c) {
    ULL d; asm("fma.rn.f32x2 %0, %1, %2, %3;" : "=l"(d) : "l"(a), "l"(b), "l"(c)); return d;
}

// ---------- fast transcendentals (exp-based, ~1e-6 rel) ----------
__device__ __forceinline__ float sig_fast(float x) {
    return __fdividef(1.0f, 1.0f + __expf(-x));
}
__device__ __forceinline__ float tanh_fast(float x) {
    float ax = fabsf(x);
    float e  = __expf(-2.0f * ax);
    float t  = __fdividef(1.0f - e, 1.0f + e);
    return copysignf(t, x);
}
__device__ __forceinline__ float elu_fast(float x) {
    float m = fminf(x, 0.0f);
    float e = __expf(m) - 1.0f;
    return e + (x - m);
}

// =====================================================================================
// Kernel 0: GI precompute, warp-per-8-rows.
// Lane k computes xp (tanh) lane-parallel for 8 rows; GEMV has lane own columns
// j = lane+32c with weights in registers; row-pairs packed f32x2; coalesced stores.
// =====================================================================================
#define GI_TILES 2
__global__ void __launch_bounds__(128) gi_kernel(
    const float* __restrict__ obs,
    const float* __restrict__ encW, const float* __restrict__ encB,
    const float* __restrict__ Wih,  const float* __restrict__ bih)
{
    __shared__ __align__(16) float sxp[4][25][12];   // [warp][k][row 0..7 + pad]

    const int wid  = threadIdx.x >> 5;
    const int lane = threadIdx.x & 31;
    const int warpg = blockIdx.x * 4 + wid;

    // weight columns j = lane, lane+32, lane+64 (j>=75 lanes hold zeros)
    float w[25][3];
    ULL bias[3];
    #pragma unroll
    for (int c = 0; c < 3; c++) {
        const int j = lane + 32 * c;
        bias[c] = (j < 75) ? pack2(bih[j], bih[j]) : 0ULL;
    }
    #pragma unroll
    for (int k = 0; k < 25; k++)
        #pragma unroll
        for (int c = 0; c < 3; c++) {
            const int j = lane + 32 * c;
            w[k][c] = (j < 75) ? Wih[k * 75 + j] : 0.f;
        }
    const int kk = (lane < 25) ? lane : 0;
    const float e0 = encW[kk], e1 = encW[25 + kk], eb = encB[kk];

    #pragma unroll
    for (int tile = 0; tile < GI_TILES; tile++) {
        const int r0 = (warpg * GI_TILES + tile) * 8;

        // lanes 0..7 load the 8 rows' observations
        float2 of2 = make_float2(0.f, 0.f);
        if (lane < 8) of2 = ((const float2*)obs)[r0 + lane];

        // lane k computes xp_k for all 8 rows
        #pragma unroll
        for (int rr = 0; rr < 8; rr++) {
            const float o0 = __shfl_sync(0xffffffffu, of2.x, rr);
            const float o1 = __shfl_sync(0xffffffffu, of2.y, rr);
            const float xp = tanh_fast(fmaf(o1, e1, fmaf(o0, e0, eb)));
            if (lane < 25) sxp[wid][lane][rr] = xp;
        }
        __syncwarp();

        ULL acc[3][4];
        #pragma unroll
        for (int c = 0; c < 3; c++)
            #pragma unroll
            for (int pp = 0; pp < 4; pp++) acc[c][pp] = bias[c];

        #pragma unroll
        for (int k = 0; k < 25; k++) {
            const float4 xa = *(const float4*)&sxp[wid][k][0];  // rows 0..3
            const float4 xb = *(const float4*)&sxp[wid][k][4];  // rows 4..7
            const ULL x01 = pack2(xa.x, xa.y);
            const ULL x23 = pack2(xa.z, xa.w);
            const ULL x45 = pack2(xb.x, xb.y);
            const ULL x67 = pack2(xb.z, xb.w);
            #pragma unroll
            for (int c = 0; c < 3; c++) {
                const ULL wk = pack2(w[k][c], w[k][c]);
                acc[c][0] = fma2(x01, wk, acc[c][0]);
                acc[c][1] = fma2(x23, wk, acc[c][1]);
                acc[c][2] = fma2(x45, wk, acc[c][2]);
                acc[c][3] = fma2(x67, wk, acc[c][3]);
            }
        }
        __syncwarp();

        // coalesced stores: for each row rr, lanes write column j = lane+32c
        #pragma unroll
        for (int rr = 0; rr < 8; rr++) {
            const size_t base = (size_t)(r0 + rr) * 75;
            #pragma unroll
            for (int c = 0; c < 3; c++) {
                const int j = lane + 32 * c;
                if (j < 75) {
                    const float2 v = unpack2(acc[c][rr >> 1]);
                    g_gi[base + j] = (rr & 1) ? v.y : v.x;
                }
            }
        }
    }
}

// =====================================================================================
// Kernel 1: reverse GRU recurrence, h-side only (GI streamed, prefetch depth 3).
// Double-buffered h in shared: one syncwarp per step.
// =====================================================================================
__global__ void __launch_bounds__(128, 3) gru_kernel(
    const float* __restrict__ Whh, const float* __restrict__ bhh,
    const float* __restrict__ stW, const float* __restrict__ stB,
    float* __restrict__ out)
{
    __shared__ __align__(16) float shh[2][4][28];

    const int wid  = threadIdx.x >> 5;
    const int lane = threadIdx.x & 31;
    const int b    = blockIdx.x * 4 + wid;
    const int i    = (lane < RNN) ? lane : (RNN - 1);

    ULL whr[14], whz[14], whn[14];
    #pragma unroll
    for (int p = 0; p < 14; p++) {
        const int k0 = 2 * p, k1 = k0 + 1;
        const float r0 = (k0 < RNN) ? Whh[k0 * 75 + i]      : 0.f;
        const float r1 = (k1 < RNN) ? Whh[k1 * 75 + i]      : 0.f;
        const float z0 = (k0 < RNN) ? Whh[k0 * 75 + i + 25] : 0.f;
        const float z1 = (k1 < RNN) ? Whh[k1 * 75 + i + 25] : 0.f;
        const float n0 = (k0 < RNN) ? Whh[k0 * 75 + i + 50] : 0.f;
        const float n1 = (k1 < RNN) ? Whh[k1 * 75 + i + 50] : 0.f;
        whr[p] = pack2(r0, r1); whz[p] = pack2(z0, z1); whn[p] = pack2(n0, n1);
    }
    const float chr = bhh[i], chz = bhh[25 + i], chn = bhh[50 + i];

    if (lane < 28) { shh[0][wid][lane] = 0.f; shh[1][wid][lane] = 0.f; }
    __syncwarp();

    float h = 0.f;
    const float* gb = g_gi + (size_t)b * SEQL * 75 + i;
    // prefetch queue depth 3: f[0] = step l, f[1] = l-1, f[2] = l-2
    float f0[3], f1[3], f2[3];
    #pragma unroll
    for (int d = 0; d < 3; d++) {
        const float* gq = gb + (199 - d) * 75;
        f0[d] = gq[0]; f1[d] = gq[25]; f2[d] = gq[50];
    }

    int pbuf = 0;
    for (int l = SEQL - 1; l >= 0; --l) {
        float p0 = 0.f, p1 = 0.f, p2 = 0.f;
        if (l >= 3) {
            const float* gq = gb + (l - 3) * 75;
            p0 = gq[0]; p1 = gq[25]; p2 = gq[50];
        }

        const ulonglong2* h4 = (const ulonglong2*)shh[pbuf][wid];
        ULL Ra = 0, Rb = 0, Za = 0, Zb = 0, Na = 0, Nb = 0;
        #pragma unroll
        for (int q = 0; q < 7; q++) {
            const ulonglong2 hv = h4[q];
            Ra = fma2(hv.x, whr[2 * q], Ra);  Rb = fma2(hv.y, whr[2 * q + 1], Rb);
            Za = fma2(hv.x, whz[2 * q], Za);  Zb = fma2(hv.y, whz[2 * q + 1], Zb);
            Na = fma2(hv.x, whn[2 * q], Na);  Nb = fma2(hv.y, whn[2 * q + 1], Nb);
        }
        const float2 ra = unpack2(Ra), rb = unpack2(Rb);
        const float2 za = unpack2(Za), zb = unpack2(Zb);
        const float2 na = unpack2(Na), nb = unpack2(Nb);
        const float ghr = (ra.x + ra.y) + (rb.x + rb.y);
        const float ghz = (za.x + za.y) + (zb.x + zb.y);
        const float ghn = (na.x + na.y) + (nb.x + nb.y);

        const float r  = sig_fast(f0[0] + chr + ghr);
        const float zg = sig_fast(f1[0] + chz + ghz);
        const float n  = tanh_fast(fmaf(r, chn + ghn, f2[0]));
        h = fmaf(zg, h - n, n);

        if (lane < RNN) shh[pbuf ^ 1][wid][lane] = h;   // write OTHER buffer
        __syncwarp();
        pbuf ^= 1;

        f0[0] = f0[1]; f1[0] = f1[1]; f2[0] = f2[1];
        f0[1] = f0[2]; f1[1] = f1[2]; f2[1] = f2[2];
        f0[2] = p0;    f1[2] = p1;    f2[2] = p2;
    }

    // final h lives in shh[pbuf]
    if (lane < 8) {
        float s = stB[lane];
        #pragma unroll
        for (int k = 0; k < RNN; k++) s = fmaf(shh[pbuf][wid][k], stW[k * 8 + lane], s);
        if (lane < 4) {
            out[Z0_OFF + b * 4 + lane] = s;
            out[MU_OFF + b * 4 + lane] = s;
        } else {
            out[LV_OFF + b * 4 + (lane - 4)] = s;
        }
    }
}

// =====================================================================================
// Kernel 2: dopri5 + FSAL + cubic-Hermite dense output (16 intervals per big step)
// + fused decoder. 4 lanes/element; lane g owns outputs o = g + 4q, q = 0..3.
// =====================================================================================
__device__ __forceinline__ void feval(
    const float (&y)[LAT], float (&k)[LAT],
    const float (&w1)[LAT][5], const float (&b1v)[5],
    const float (&w2)[5][LAT], const float (&b2v)[LAT])
{
    float v[5];
    #pragma unroll
    for (int u = 0; u < 5; u++) {
        float t = b1v[u];
        #pragma unroll
        for (int c = 0; c < LAT; c++) t = fmaf(y[c], w1[c][u], t);
        v[u] = elu_fast(t);
    }
    #pragma unroll
    for (int i = 0; i < LAT; i++) {
        float a  = fmaf(v[0], w2[0][i], v[1] * w2[1][i]);
        float bq = fmaf(v[2], w2[2][i], v[3] * w2[3][i]);
        float s  = fmaf(v[4], w2[4][i], a + bq);
        s += __shfl_xor_sync(0xffffffffu, s, 1);
        s += __shfl_xor_sync(0xffffffffu, s, 2);
        k[i] = s + b2v[i];
    }
}

__device__ __forceinline__ void decode_store(
    const float (&zg)[LAT],
    const float4* __restrict__ sW1, const float2* __restrict__ sW2,
    const float*  __restrict__ sb1, float b20, float b21,
    float* __restrict__ out, int tt, int b)
{
    float x0 = b20, x1 = b21;
    #pragma unroll
    for (int u = 0; u < ODEH; u++) {
        const float4 wv = sW1[u];
        float t = sb1[u];
        t = fmaf(zg[0], wv.x, t);
        t = fmaf(zg[1], wv.y, t);
        t = fmaf(zg[2], wv.z, t);
        t = fmaf(zg[3], wv.w, t);
        t = fmaxf(t, 0.0f);
        const float2 w2v = sW2[u];
        x0 = fmaf(t, w2v.x, x0);
        x1 = fmaf(t, w2v.y, x1);
    }
    float2 ov = {x0, x1};
    *(float2*)(out + XP_OFF + ((size_t)tt * BATCH + b) * 2) = ov;
}

__global__ void __launch_bounds__(128) ode_kernel(
    const float* __restrict__ pt,
    const float* __restrict__ W1,  const float* __restrict__ B1,
    const float* __restrict__ W2,  const float* __restrict__ B2,
    const float* __restrict__ dW1, const float* __restrict__ dB1,
    const float* __restrict__ dW2, const float* __restrict__ dB2,
    float* __restrict__ out)
{
    __shared__ float  spt[NT];
    __shared__ float4 sW1[ODEH];
    __shared__ float2 sW2[ODEH];
    __shared__ float  sb1[ODEH];

    const int tid = threadIdx.x;
    for (int idx = tid; idx < NT; idx += 128) spt[idx] = pt[idx];
    if (tid < ODEH) {
        sW1[tid] = make_float4(dW1[tid], dW1[ODEH + tid], dW1[2 * ODEH + tid], dW1[3 * ODEH + tid]);
        sW2[tid] = make_float2(dW2[tid * 2], dW2[tid * 2 + 1]);
        sb1[tid] = dB1[tid];
    }
    __syncthreads();

    const int gtid = blockIdx.x * 128 + tid;
    const int b    = gtid >> 2;
    const int g    = gtid & 3;
    const float b20 = dB2[0], b21 = dB2[1];

    float w1[LAT][5], b1v[5], w2[5][LAT], b2v[LAT];
    #pragma unroll
    for (int u = 0; u < 5; u++) {
        const int j = g * 5 + u;
        b1v[u] = B1[j];
        #pragma unroll
        for (int c = 0; c < LAT; c++) w1[c][u] = W1[c * ODEH + j];
        #pragma unroll
        for (int i = 0; i < LAT; i++) w2[u][i] = W2[j * LAT + i];
    }
    #pragma unroll
    for (int i = 0; i < LAT; i++) b2v[i] = B2[i];

    const float4 z0v = *(const float4*)(out + Z0_OFF + (size_t)b * 4);
    float z[LAT] = {z0v.x, z0v.y, z0v.z, z0v.w};
    if (g == 0) {
        *(float4*)(out + ZT_OFF + (size_t)b * 4) = z0v;
        decode_store(z, sW1, sW2, sb1, b20, b21, out, 0, b);
    }

    const float A21 = 0.2f;
    const float A31 = 3.0f/40.0f,       A32 = 9.0f/40.0f;
    const float A41 = 44.0f/45.0f,      A42 = -56.0f/15.0f,      A43 = 32.0f/9.0f;
    const float A51 = 19372.0f/6561.0f, A52 = -25360.0f/2187.0f, A53 = 64448.0f/6561.0f, A54 = -212.0f/729.0f;
    const float A61 = 9017.0f/3168.0f,  A62 = -355.0f/33.0f,     A63 = 46732.0f/5247.0f,
                A64 = 49.0f/176.0f,     A65 = -5103.0f/18656.0f;
    const float BB1 = 35.0f/384.0f,     BB3 = 500.0f/1113.0f,    BB4 = 125.0f/192.0f,
                BB5 = -2187.0f/6784.0f, BB6 = 11.0f/84.0f;

    float k1[LAT], k2[LAT], k3[LAT], k4[LAT], k5[LAT], k6[LAT], k7[LAT], y[LAT], z1[LAT];

    feval(z, k1, w1, b1v, w2, b2v);   // initial (FSAL thereafter)

    int m = 0;
    #pragma unroll 1
    for (int grp = 0; grp < 32; ++grp) {
        const int n = (grp < 31) ? 16 : 3;          // 499 = 31*16 + 3
        const float pt0 = spt[m];
        const float h   = spt[m + n] - pt0;

        #pragma unroll
        for (int i = 0; i < LAT; i++) y[i] = fmaf(h, A21 * k1[i], z[i]);
        feval(y, k2, w1, b1v, w2, b2v);
        #pragma unroll
        for (int i = 0; i < LAT; i++) {
            float s = fmaf(A32, k2[i], A31 * k1[i]);
            y[i] = fmaf(h, s, z[i]);
        }
        feval(y, k3, w1, b1v, w2, b2v);
        #pragma unroll
        for (int i = 0; i < LAT; i++) {
            float s = fmaf(A43, k3[i], fmaf(A42, k2[i], A41 * k1[i]));
            y[i] = fmaf(h, s, z[i]);
        }
        feval(y, k4, w1, b1v, w2, b2v);
        #pragma unroll
        for (int i = 0; i < LAT; i++) {
            float s = fmaf(A54, k4[i], fmaf(A53, k3[i], fmaf(A52, k2[i], A51 * k1[i])));
            y[i] = fmaf(h, s, z[i]);
        }
        feval(y, k5, w1, b1v, w2, b2v);
        #pragma unroll
        for (int i = 0; i < LAT; i++) {
            float s = fmaf(A65, k5[i], fmaf(A64, k4[i], fmaf(A63, k3[i], fmaf(A62, k2[i], A61 * k1[i]))));
            y[i] = fmaf(h, s, z[i]);
        }
        feval(y, k6, w1, b1v, w2, b2v);
        #pragma unroll
        for (int i = 0; i < LAT; i++) {
            float s = fmaf(BB6, k6[i], fmaf(BB5, k5[i], fmaf(BB4, k4[i], fmaf(BB3, k3[i], BB1 * k1[i]))));
            z1[i] = fmaf(h, s, z[i]);
        }
        feval(z1, k7, w1, b1v, w2, b2v);  // FSAL: k7 = f(z1) = next k1

        // lane g handles outputs o = g + 4q (o < n); o == n-1 uses exact z1
        #pragma unroll
        for (int q = 0; q < 4; q++) {
            const int o = g + q * 4;
            if (o < n) {
                const int tt = m + 1 + o;
                float zg[LAT];
                if (o == n - 1) {
                    #pragma unroll
                    for (int i = 0; i < LAT; i++) zg[i] = z1[i];
                } else {
                    const float s  = __fdividef(spt[tt] - pt0, h);
                    const float s2 = s * s;
                    const float s3 = s2 * s;
                    const float c0 = 2.0f * s3 - 3.0f * s2 + 1.0f;
                    const float c1 = (s3 - 2.0f * s2 + s) * h;
                    const float c2 = 3.0f * s2 - 2.0f * s3;
                    const float c3 = (s3 - s2) * h;
                    #pragma unroll
                    for (int i = 0; i < LAT; i++)
                        zg[i] = fmaf(c3, k7[i], fmaf(c2, z1[i], fmaf(c1, k1[i], c0 * z[i])));
                }
                float4 zo = {zg[0], zg[1], zg[2], zg[3]};
                *(float4*)(out + ZT_OFF + ((size_t)tt * BATCH + b) * 4) = zo;
                decode_store(zg, sW1, sW2, sb1, b20, b21, out, tt, b);
            }
        }

        #pragma unroll
        for (int i = 0; i < LAT; i++) { z[i] = z1[i]; k1[i] = k7[i]; }
        m += n;
    }
}

// =====================================================================================
extern "C" void kernel_launch(void* const* d_in, const int* in_sizes, int n_in,
                              void* d_out, int out_size)
{
    const float* obs   = (const float*)d_in[0];
    const float* pt    = (const float*)d_in[1];
    const float* encW  = (const float*)d_in[2];
    const float* encB  = (const float*)d_in[3];
    const float* Wih   = (const float*)d_in[4];
    const float* Whh   = (const float*)d_in[5];
    const float* bih   = (const float*)d_in[6];
    const float* bhh   = (const float*)d_in[7];
    const float* stW   = (const float*)d_in[8];
    const float* stB   = (const float*)d_in[9];
    const float* oW1   = (const float*)d_in[10];
    const float* ob1   = (const float*)d_in[11];
    const float* oW2   = (const float*)d_in[12];
    const float* ob2   = (const float*)d_in[13];
    const float* dW1   = (const float*)d_in[14];
    const float* db1   = (const float*)d_in[15];
    const float* dW2   = (const float*)d_in[16];
    const float* db2   = (const float*)d_in[17];
    float* out = (float*)d_out;

    // rows = 819200 = 12800 blocks * 4 warps * GI_TILES(2) * 8 rows
    gi_kernel<<<12800, 128>>>(obs, encW, encB, Wih, bih);
    gru_kernel<<<BATCH / 4, 128>>>(Whh, bhh, stW, stB, out);
    ode_kernel<<<(BATCH * 4) / 128, 128>>>(pt, oW1, ob1, oW2, ob2, dW1, db1, dW2, db2, out);
}

// round 9
// speedup vs baseline: 1.3651x; 1.1511x over previous
#include <cuda_runtime.h>

#define BATCH 4096
#define SEQL  200
#define NT    500
#define OBS   2
#define LAT   4
#define RNN   25
#define ODEH  20

// Output layout: x_pred [T,B,OBS] | z_traj [T,B,LAT] | z0 [B,LAT] | mu [B,LAT] | logvar [B,LAT]
#define XP_OFF 0
#define ZT_OFF (NT * BATCH * OBS)
#define Z0_OFF (ZT_OFF + NT * BATCH * LAT)
#define MU_OFF (Z0_OFF + BATCH * LAT)
#define LV_OFF (MU_OFF + BATCH * LAT)

typedef unsigned long long ULL;

// ---------- f32x2 packed helpers ----------
__device__ __forceinline__ ULL pack2(float lo, float hi) {
    ULL r; asm("mov.b64 %0, {%1, %2};" : "=l"(r) : "f"(lo), "f"(hi)); return r;
}
__device__ __forceinline__ float2 unpack2(ULL v) {
    float2 r; asm("mov.b64 {%0, %1}, %2;" : "=f"(r.x), "=f"(r.y) : "l"(v)); return r;
}
__device__ __forceinline__ ULL fma2(ULL a, ULL b, ULL c) {
    ULL d; asm("fma.rn.f32x2 %0, %1, %2, %3;" : "=l"(d) : "l"(a), "l"(b), "l"(c)); return d;
}

// ---------- fast transcendentals (exp-based, ~1e-6 rel) ----------
__device__ __forceinline__ float sig_fast(float x) {
    return __fdividef(1.0f, 1.0f + __expf(-x));
}
__device__ __forceinline__ float tanh_fast(float x) {
    float ax = fabsf(x);
    float e  = __expf(-2.0f * ax);
    float t  = __fdividef(1.0f - e, 1.0f + e);
    return copysignf(t, x);
}
__device__ __forceinline__ float elu_fast(float x) {
    float m = fminf(x, 0.0f);
    float e = __expf(m) - 1.0f;
    return e + (x - m);
}

// =====================================================================================
// Kernel 1: single-warp fused reverse GRU. One warp per batch element; the warp
// alternates: produce GI for an 8-step chunk (round-6 gi_kernel tile, proven) into
// its private smem slice, then consume those 8 steps (round-6 gru_kernel recurrence,
// proven). Only __syncwarp — no cross-warp synchronization at all.
// =====================================================================================
__global__ void __launch_bounds__(128) gru_fused_kernel(
    const float* __restrict__ obs,
    const float* __restrict__ encW, const float* __restrict__ encB,
    const float* __restrict__ Wih,  const float* __restrict__ bih,
    const float* __restrict__ Whh,  const float* __restrict__ bhh,
    const float* __restrict__ stW,  const float* __restrict__ stB,
    float* __restrict__ out)
{
    __shared__ __align__(16) float sxp[4][25][12];  // [warp][k][row 0..7 + pad]
    __shared__ __align__(16) float sxg[4][8][76];   // [warp][step-in-chunk][gi column]
    __shared__ __align__(16) float shh[4][2][28];   // [warp][buf][h]

    const int wid  = threadIdx.x >> 5;
    const int lane = threadIdx.x & 31;
    const int b    = blockIdx.x * 4 + wid;
    const int i    = (lane < RNN) ? lane : (RNN - 1);

    // ---- producer weights: Wih columns j = lane + 32c in registers ----
    float w[25][3];
    ULL bias[3];
    #pragma unroll
    for (int c = 0; c < 3; c++) {
        const int j = lane + 32 * c;
        bias[c] = (j < 75) ? pack2(bih[j], bih[j]) : 0ULL;
    }
    #pragma unroll
    for (int k = 0; k < 25; k++)
        #pragma unroll
        for (int c = 0; c < 3; c++) {
            const int j = lane + 32 * c;
            w[k][c] = (j < 75) ? Wih[k * 75 + j] : 0.f;
        }
    const int kk = (lane < 25) ? lane : 0;
    const float e0 = encW[kk], e1 = encW[25 + kk], eb = encB[kk];
    const float2* ob2 = (const float2*)obs + (size_t)b * SEQL;

    // ---- consumer weights: Whh gate-column i packed over k-pairs ----
    ULL whr[14], whz[14], whn[14];
    #pragma unroll
    for (int p = 0; p < 14; p++) {
        const int k0 = 2 * p, k1 = k0 + 1;
        const float r0 = (k0 < RNN) ? Whh[k0 * 75 + i]      : 0.f;
        const float r1 = (k1 < RNN) ? Whh[k1 * 75 + i]      : 0.f;
        const float z0 = (k0 < RNN) ? Whh[k0 * 75 + i + 25] : 0.f;
        const float z1 = (k1 < RNN) ? Whh[k1 * 75 + i + 25] : 0.f;
        const float n0 = (k0 < RNN) ? Whh[k0 * 75 + i + 50] : 0.f;
        const float n1 = (k1 < RNN) ? Whh[k1 * 75 + i + 50] : 0.f;
        whr[p] = pack2(r0, r1); whz[p] = pack2(z0, z1); whn[p] = pack2(n0, n1);
    }
    const float chr = bhh[i], chz = bhh[25 + i], chn = bhh[50 + i];

    if (lane < 28) { shh[wid][0][lane] = 0.f; shh[wid][1][lane] = 0.f; }
    __syncwarp();

    float h = 0.f;
    int pbuf = 0;

    #pragma unroll 1
    for (int c = 0; c < 25; c++) {
        // ================= produce chunk c: l = 199-8c-rr, rr = 0..7 =================
        const int l_hi = 199 - 8 * c;
        float2 of2 = make_float2(0.f, 0.f);
        if (lane < 8) of2 = ob2[l_hi - lane];
        #pragma unroll
        for (int rr = 0; rr < 8; rr++) {
            const float o0 = __shfl_sync(0xffffffffu, of2.x, rr);
            const float o1 = __shfl_sync(0xffffffffu, of2.y, rr);
            const float xp = tanh_fast(fmaf(o1, e1, fmaf(o0, e0, eb)));
            if (lane < 25) sxp[wid][lane][rr] = xp;
        }
        __syncwarp();

        ULL acc[3][4];
        #pragma unroll
        for (int cc = 0; cc < 3; cc++)
            #pragma unroll
            for (int pp = 0; pp < 4; pp++) acc[cc][pp] = bias[cc];

        #pragma unroll
        for (int k = 0; k < 25; k++) {
            const float4 xa = *(const float4*)&sxp[wid][k][0];   // rows 0..3
            const float4 xb = *(const float4*)&sxp[wid][k][4];   // rows 4..7
            const ULL x01 = pack2(xa.x, xa.y);
            const ULL x23 = pack2(xa.z, xa.w);
            const ULL x45 = pack2(xb.x, xb.y);
            const ULL x67 = pack2(xb.z, xb.w);
            #pragma unroll
            for (int cc = 0; cc < 3; cc++) {
                const ULL wk = pack2(w[k][cc], w[k][cc]);
                acc[cc][0] = fma2(x01, wk, acc[cc][0]);
                acc[cc][1] = fma2(x23, wk, acc[cc][1]);
                acc[cc][2] = fma2(x45, wk, acc[cc][2]);
                acc[cc][3] = fma2(x67, wk, acc[cc][3]);
            }
        }
        #pragma unroll
        for (int rr = 0; rr < 8; rr++) {
            #pragma unroll
            for (int cc = 0; cc < 3; cc++) {
                const int j = lane + 32 * cc;
                if (j < 75) {
                    const float2 v = unpack2(acc[cc][rr >> 1]);
                    sxg[wid][rr][j] = (rr & 1) ? v.y : v.x;
                }
            }
        }
        __syncwarp();

        // ================= consume 8 steps =================
        #pragma unroll
        for (int s = 0; s < 8; s++) {
            const float gir = sxg[wid][s][i];
            const float giz = sxg[wid][s][25 + i];
            const float gin = sxg[wid][s][50 + i];

            const ulonglong2* h4 = (const ulonglong2*)shh[wid][pbuf];
            ULL Ra = 0, Rb = 0, Za = 0, Zb = 0, Na = 0, Nb = 0;
            #pragma unroll
            for (int q = 0; q < 7; q++) {
                const ulonglong2 hv = h4[q];
                Ra = fma2(hv.x, whr[2 * q], Ra);  Rb = fma2(hv.y, whr[2 * q + 1], Rb);
                Za = fma2(hv.x, whz[2 * q], Za);  Zb = fma2(hv.y, whz[2 * q + 1], Zb);
                Na = fma2(hv.x, whn[2 * q], Na);  Nb = fma2(hv.y, whn[2 * q + 1], Nb);
            }
            const float2 ra = unpack2(Ra), rb = unpack2(Rb);
            const float2 za = unpack2(Za), zb = unpack2(Zb);
            const float2 na = unpack2(Na), nb = unpack2(Nb);
            const float ghr = (ra.x + ra.y) + (rb.x + rb.y);
            const float ghz = (za.x + za.y) + (zb.x + zb.y);
            const float ghn = (na.x + na.y) + (nb.x + nb.y);

            const float r  = sig_fast(gir + chr + ghr);
            const float zg = sig_fast(giz + chz + ghz);
            const float n  = tanh_fast(fmaf(r, chn + ghn, gin));
            h = fmaf(zg, h - n, n);

            if (lane < RNN) shh[wid][pbuf ^ 1][lane] = h;
            __syncwarp();
            pbuf ^= 1;
        }
    }

    // stats head: lanes 0..7 -> mu (0..3) / logvar (4..7)
    if (lane < 8) {
        float s = stB[lane];
        #pragma unroll
        for (int k = 0; k < RNN; k++) s = fmaf(shh[wid][pbuf][k], stW[k * 8 + lane], s);
        if (lane < 4) {
            out[Z0_OFF + b * 4 + lane] = s;
            out[MU_OFF + b * 4 + lane] = s;
        } else {
            out[LV_OFF + b * 4 + (lane - 4)] = s;
        }
    }
}

// =====================================================================================
// Kernel 2: dopri5 + FSAL + cubic-Hermite dense output (16 intervals per big step)
// + fused decoder. (Byte-identical to the round-6 passing version.)
// =====================================================================================
__device__ __forceinline__ void feval(
    const float (&y)[LAT], float (&k)[LAT],
    const float (&w1)[LAT][5], const float (&b1v)[5],
    const float (&w2)[5][LAT], const float (&b2v)[LAT])
{
    float v[5];
    #pragma unroll
    for (int u = 0; u < 5; u++) {
        float t = b1v[u];
        #pragma unroll
        for (int c = 0; c < LAT; c++) t = fmaf(y[c], w1[c][u], t);
        v[u] = elu_fast(t);
    }
    #pragma unroll
    for (int i = 0; i < LAT; i++) {
        float a  = fmaf(v[0], w2[0][i], v[1] * w2[1][i]);
        float bq = fmaf(v[2], w2[2][i], v[3] * w2[3][i]);
        float s  = fmaf(v[4], w2[4][i], a + bq);
        s += __shfl_xor_sync(0xffffffffu, s, 1);
        s += __shfl_xor_sync(0xffffffffu, s, 2);
        k[i] = s + b2v[i];
    }
}

__device__ __forceinline__ void decode_store(
    const float (&zg)[LAT],
    const float4* __restrict__ sW1, const float2* __restrict__ sW2,
    const float*  __restrict__ sb1, float b20, float b21,
    float* __restrict__ out, int tt, int b)
{
    float x0 = b20, x1 = b21;
    #pragma unroll
    for (int u = 0; u < ODEH; u++) {
        const float4 wv = sW1[u];
        float t = sb1[u];
        t = fmaf(zg[0], wv.x, t);
        t = fmaf(zg[1], wv.y, t);
        t = fmaf(zg[2], wv.z, t);
        t = fmaf(zg[3], wv.w, t);
        t = fmaxf(t, 0.0f);
        const float2 w2v = sW2[u];
        x0 = fmaf(t, w2v.x, x0);
        x1 = fmaf(t, w2v.y, x1);
    }
    float2 ov = {x0, x1};
    *(float2*)(out + XP_OFF + ((size_t)tt * BATCH + b) * 2) = ov;
}

__global__ void __launch_bounds__(128) ode_kernel(
    const float* __restrict__ pt,
    const float* __restrict__ W1,  const float* __restrict__ B1,
    const float* __restrict__ W2,  const float* __restrict__ B2,
    const float* __restrict__ dW1, const float* __restrict__ dB1,
    const float* __restrict__ dW2, const float* __restrict__ dB2,
    float* __restrict__ out)
{
    __shared__ float  spt[NT];
    __shared__ float4 sW1[ODEH];
    __shared__ float2 sW2[ODEH];
    __shared__ float  sb1[ODEH];

    const int tid = threadIdx.x;
    for (int idx = tid; idx < NT; idx += 128) spt[idx] = pt[idx];
    if (tid < ODEH) {
        sW1[tid] = make_float4(dW1[tid], dW1[ODEH + tid], dW1[2 * ODEH + tid], dW1[3 * ODEH + tid]);
        sW2[tid] = make_float2(dW2[tid * 2], dW2[tid * 2 + 1]);
        sb1[tid] = dB1[tid];
    }
    __syncthreads();

    const int gtid = blockIdx.x * 128 + tid;
    const int b    = gtid >> 2;
    const int g    = gtid & 3;
    const float b20 = dB2[0], b21 = dB2[1];

    float w1[LAT][5], b1v[5], w2[5][LAT], b2v[LAT];
    #pragma unroll
    for (int u = 0; u < 5; u++) {
        const int j = g * 5 + u;
        b1v[u] = B1[j];
        #pragma unroll
        for (int c = 0; c < LAT; c++) w1[c][u] = W1[c * ODEH + j];
        #pragma unroll
        for (int i = 0; i < LAT; i++) w2[u][i] = W2[j * LAT + i];
    }
    #pragma unroll
    for (int i = 0; i < LAT; i++) b2v[i] = B2[i];

    const float4 z0v = *(const float4*)(out + Z0_OFF + (size_t)b * 4);
    float z[LAT] = {z0v.x, z0v.y, z0v.z, z0v.w};
    if (g == 0) {
        *(float4*)(out + ZT_OFF + (size_t)b * 4) = z0v;
        decode_store(z, sW1, sW2, sb1, b20, b21, out, 0, b);
    }

    const float A21 = 0.2f;
    const float A31 = 3.0f/40.0f,       A32 = 9.0f/40.0f;
    const float A41 = 44.0f/45.0f,      A42 = -56.0f/15.0f,      A43 = 32.0f/9.0f;
    const float A51 = 19372.0f/6561.0f, A52 = -25360.0f/2187.0f, A53 = 64448.0f/6561.0f, A54 = -212.0f/729.0f;
    const float A61 = 9017.0f/3168.0f,  A62 = -355.0f/33.0f,     A63 = 46732.0f/5247.0f,
                A64 = 49.0f/176.0f,     A65 = -5103.0f/18656.0f;
    const float BB1 = 35.0f/384.0f,     BB3 = 500.0f/1113.0f,    BB4 = 125.0f/192.0f,
                BB5 = -2187.0f/6784.0f, BB6 = 11.0f/84.0f;

    float k1[LAT], k2[LAT], k3[LAT], k4[LAT], k5[LAT], k6[LAT], k7[LAT], y[LAT], z1[LAT];

    feval(z, k1, w1, b1v, w2, b2v);   // initial (FSAL thereafter)

    int m = 0;
    #pragma unroll 1
    for (int grp = 0; grp < 32; ++grp) {
        const int n = (grp < 31) ? 16 : 3;          // 499 = 31*16 + 3
        const float pt0 = spt[m];
        const float h   = spt[m + n] - pt0;

        #pragma unroll
        for (int i = 0; i < LAT; i++) y[i] = fmaf(h, A21 * k1[i], z[i]);
        feval(y, k2, w1, b1v, w2, b2v);
        #pragma unroll
        for (int i = 0; i < LAT; i++) {
            float s = fmaf(A32, k2[i], A31 * k1[i]);
            y[i] = fmaf(h, s, z[i]);
        }
        feval(y, k3, w1, b1v, w2, b2v);
        #pragma unroll
        for (int i = 0; i < LAT; i++) {
            float s = fmaf(A43, k3[i], fmaf(A42, k2[i], A41 * k1[i]));
            y[i] = fmaf(h, s, z[i]);
        }
        feval(y, k4, w1, b1v, w2, b2v);
        #pragma unroll
        for (int i = 0; i < LAT; i++) {
            float s = fmaf(A54, k4[i], fmaf(A53, k3[i], fmaf(A52, k2[i], A51 * k1[i])));
            y[i] = fmaf(h, s, z[i]);
        }
        feval(y, k5, w1, b1v, w2, b2v);
        #pragma unroll
        for (int i = 0; i < LAT; i++) {
            float s = fmaf(A65, k5[i], fmaf(A64, k4[i], fmaf(A63, k3[i], fmaf(A62, k2[i], A61 * k1[i]))));
            y[i] = fmaf(h, s, z[i]);
        }
        feval(y, k6, w1, b1v, w2, b2v);
        #pragma unroll
        for (int i = 0; i < LAT; i++) {
            float s = fmaf(BB6, k6[i], fmaf(BB5, k5[i], fmaf(BB4, k4[i], fmaf(BB3, k3[i], BB1 * k1[i]))));
            z1[i] = fmaf(h, s, z[i]);
        }
        feval(z1, k7, w1, b1v, w2, b2v);  // FSAL: k7 = f(z1) = next k1

        // lane g handles outputs o = g + 4q (o < n); o == n-1 uses exact z1
        #pragma unroll
        for (int q = 0; q < 4; q++) {
            const int o = g + q * 4;
            if (o < n) {
                const int tt = m + 1 + o;
                float zg[LAT];
                if (o == n - 1) {
                    #pragma unroll
                    for (int i = 0; i < LAT; i++) zg[i] = z1[i];
                } else {
                    const float s  = __fdividef(spt[tt] - pt0, h);
                    const float s2 = s * s;
                    const float s3 = s2 * s;
                    const float c0 = 2.0f * s3 - 3.0f * s2 + 1.0f;
                    const float c1 = (s3 - 2.0f * s2 + s) * h;
                    const float c2 = 3.0f * s2 - 2.0f * s3;
                    const float c3 = (s3 - s2) * h;
                    #pragma unroll
                    for (int i = 0; i < LAT; i++)
                        zg[i] = fmaf(c3, k7[i], fmaf(c2, z1[i], fmaf(c1, k1[i], c0 * z[i])));
                }
                float4 zo = {zg[0], zg[1], zg[2], zg[3]};
                *(float4*)(out + ZT_OFF + ((size_t)tt * BATCH + b) * 4) = zo;
                decode_store(zg, sW1, sW2, sb1, b20, b21, out, tt, b);
            }
        }

        #pragma unroll
        for (int i = 0; i < LAT; i++) { z[i] = z1[i]; k1[i] = k7[i]; }
        m += n;
    }
}

// =====================================================================================
extern "C" void kernel_launch(void* const* d_in, const int* in_sizes, int n_in,
                              void* d_out, int out_size)
{
    const float* obs   = (const float*)d_in[0];
    const float* pt    = (const float*)d_in[1];
    const float* encW  = (const float*)d_in[2];
    const float* encB  = (const float*)d_in[3];
    const float* Wih   = (const float*)d_in[4];
    const float* Whh   = (const float*)d_in[5];
    const float* bih   = (const float*)d_in[6];
    const float* bhh   = (const float*)d_in[7];
    const float* stW   = (const float*)d_in[8];
    const float* stB   = (const float*)d_in[9];
    const float* oW1   = (const float*)d_in[10];
    const float* ob1   = (const float*)d_in[11];
    const float* oW2   = (const float*)d_in[12];
    const float* ob2   = (const float*)d_in[13];
    const float* dW1   = (const float*)d_in[14];
    const float* db1   = (const float*)d_in[15];
    const float* dW2   = (const float*)d_in[16];
    const float* db2   = (const float*)d_in[17];
    float* out = (float*)d_out;

    gru_fused_kernel<<<BATCH / 4, 128>>>(obs, encW, encB, Wih, bih, Whh, bhh, stW, stB, out);
    ode_kernel<<<(BATCH * 4) / 128, 128>>>(pt, oW1, ob1, oW2, ob2, dW1, db1, dW2, db2, out);
}

// round 10
// speedup vs baseline: 1.5277x; 1.1191x over previous
#include <cuda_runtime.h>

#define BATCH 4096
#define SEQL  200
#define NT    500
#define OBS   2
#define LAT   4
#define RNN   25
#define ODEH  20

// Output layout: x_pred [T,B,OBS] | z_traj [T,B,LAT] | z0 [B,LAT] | mu [B,LAT] | logvar [B,LAT]
#define XP_OFF 0
#define ZT_OFF (NT * BATCH * OBS)
#define Z0_OFF (ZT_OFF + NT * BATCH * LAT)
#define MU_OFF (Z0_OFF + BATCH * LAT)
#define LV_OFF (MU_OFF + BATCH * LAT)

typedef unsigned long long ULL;

// ---------- f32x2 packed helpers ----------
__device__ __forceinline__ ULL pack2(float lo, float hi) {
    ULL r; asm("mov.b64 %0, {%1, %2};" : "=l"(r) : "f"(lo), "f"(hi)); return r;
}
__device__ __forceinline__ float2 unpack2(ULL v) {
    float2 r; asm("mov.b64 {%0, %1}, %2;" : "=f"(r.x), "=f"(r.y) : "l"(v)); return r;
}
__device__ __forceinline__ ULL fma2(ULL a, ULL b, ULL c) {
    ULL d; asm("fma.rn.f32x2 %0, %1, %2, %3;" : "=l"(d) : "l"(a), "l"(b), "l"(c)); return d;
}

// ---------- fast transcendentals (exp-based, ~1e-6 rel) ----------
__device__ __forceinline__ float sig_fast(float x) {
    return __fdividef(1.0f, 1.0f + __expf(-x));
}
__device__ __forceinline__ float tanh_fast(float x) {
    float ax = fabsf(x);
    float e  = __expf(-2.0f * ax);
    float t  = __fdividef(1.0f - e, 1.0f + e);
    return copysignf(t, x);
}
__device__ __forceinline__ float elu_fast(float x) {
    float m = fminf(x, 0.0f);
    float e = __expf(m) - 1.0f;
    return e + (x - m);
}

// =====================================================================================
// Kernel 1: single-warp fused reverse GRU (round-9 structure, proven). One warp per
// element alternates produce(8-step GI chunk)/consume(8 recurrence steps). Change vs
// round 9: producer Wih columns read from block-shared sWih instead of 81 registers
// (uniform __syncthreads fill at kernel start), __launch_bounds__(128,4) for occupancy.
// =====================================================================================
__global__ void __launch_bounds__(128, 4) gru_fused_kernel(
    const float* __restrict__ obs,
    const float* __restrict__ encW, const float* __restrict__ encB,
    const float* __restrict__ Wih,  const float* __restrict__ bih,
    const float* __restrict__ Whh,  const float* __restrict__ bhh,
    const float* __restrict__ stW,  const float* __restrict__ stB,
    float* __restrict__ out)
{
    __shared__ __align__(16) float sWih[25][76];    // Wih row-major, col 75 = zero pad
    __shared__ __align__(16) float sxp[4][25][12];  // [warp][k][row 0..7 + pad]
    __shared__ __align__(16) float sxg[4][8][76];   // [warp][step-in-chunk][gi column]
    __shared__ __align__(16) float shh[4][2][28];   // [warp][buf][h]

    const int tid  = threadIdx.x;
    const int wid  = tid >> 5;
    const int lane = tid & 31;
    const int b    = blockIdx.x * 4 + wid;
    const int i    = (lane < RNN) ? lane : (RNN - 1);

    // cooperative fill of sWih (uniform across all warps, then one uniform barrier)
    for (int idx = tid; idx < 25 * 76; idx += 128) {
        const int k = idx / 76, j = idx - k * 76;
        sWih[k][j] = (j < 75) ? Wih[k * 75 + j] : 0.f;
    }
    __syncthreads();

    // ---- producer per-lane constants ----
    ULL bias[3];
    #pragma unroll
    for (int c = 0; c < 3; c++) {
        const int j = lane + 32 * c;
        bias[c] = (j < 75) ? pack2(bih[j], bih[j]) : 0ULL;
    }
    const int j2 = (lane + 64 < 75) ? (lane + 64) : 75;     // col 75 is zero pad
    const int kk = (lane < 25) ? lane : 0;
    const float e0 = encW[kk], e1 = encW[25 + kk], eb = encB[kk];
    const float2* ob2 = (const float2*)obs + (size_t)b * SEQL;

    // ---- consumer weights: Whh gate-column i packed over k-pairs (registers) ----
    ULL whr[14], whz[14], whn[14];
    #pragma unroll
    for (int p = 0; p < 14; p++) {
        const int k0 = 2 * p, k1 = k0 + 1;
        const float r0 = (k0 < RNN) ? Whh[k0 * 75 + i]      : 0.f;
        const float r1 = (k1 < RNN) ? Whh[k1 * 75 + i]      : 0.f;
        const float z0 = (k0 < RNN) ? Whh[k0 * 75 + i + 25] : 0.f;
        const float z1 = (k1 < RNN) ? Whh[k1 * 75 + i + 25] : 0.f;
        const float n0 = (k0 < RNN) ? Whh[k0 * 75 + i + 50] : 0.f;
        const float n1 = (k1 < RNN) ? Whh[k1 * 75 + i + 50] : 0.f;
        whr[p] = pack2(r0, r1); whz[p] = pack2(z0, z1); whn[p] = pack2(n0, n1);
    }
    const float chr = bhh[i], chz = bhh[25 + i], chn = bhh[50 + i];

    if (lane < 28) { shh[wid][0][lane] = 0.f; shh[wid][1][lane] = 0.f; }
    __syncwarp();

    float h = 0.f;
    int pbuf = 0;

    #pragma unroll 1
    for (int c = 0; c < 25; c++) {
        // ================= produce chunk c: l = 199-8c-rr, rr = 0..7 =================
        const int l_hi = 199 - 8 * c;
        float2 of2 = make_float2(0.f, 0.f);
        if (lane < 8) of2 = ob2[l_hi - lane];
        #pragma unroll
        for (int rr = 0; rr < 8; rr++) {
            const float o0 = __shfl_sync(0xffffffffu, of2.x, rr);
            const float o1 = __shfl_sync(0xffffffffu, of2.y, rr);
            const float xp = tanh_fast(fmaf(o1, e1, fmaf(o0, e0, eb)));
            if (lane < 25) sxp[wid][lane][rr] = xp;
        }
        __syncwarp();

        ULL acc[3][4];
        #pragma unroll
        for (int cc = 0; cc < 3; cc++)
            #pragma unroll
            for (int pp = 0; pp < 4; pp++) acc[cc][pp] = bias[cc];

        #pragma unroll 5
        for (int k = 0; k < 25; k++) {
            const float4 xa = *(const float4*)&sxp[wid][k][0];   // rows 0..3
            const float4 xb = *(const float4*)&sxp[wid][k][4];   // rows 4..7
            const ULL x01 = pack2(xa.x, xa.y);
            const ULL x23 = pack2(xa.z, xa.w);
            const ULL x45 = pack2(xb.x, xb.y);
            const ULL x67 = pack2(xb.z, xb.w);
            const float w0 = sWih[k][lane];
            const float w1 = sWih[k][lane + 32];
            const float w2 = sWih[k][j2];
            const ULL wk0 = pack2(w0, w0);
            const ULL wk1 = pack2(w1, w1);
            const ULL wk2 = pack2(w2, w2);
            acc[0][0] = fma2(x01, wk0, acc[0][0]);
            acc[0][1] = fma2(x23, wk0, acc[0][1]);
            acc[0][2] = fma2(x45, wk0, acc[0][2]);
            acc[0][3] = fma2(x67, wk0, acc[0][3]);
            acc[1][0] = fma2(x01, wk1, acc[1][0]);
            acc[1][1] = fma2(x23, wk1, acc[1][1]);
            acc[1][2] = fma2(x45, wk1, acc[1][2]);
            acc[1][3] = fma2(x67, wk1, acc[1][3]);
            acc[2][0] = fma2(x01, wk2, acc[2][0]);
            acc[2][1] = fma2(x23, wk2, acc[2][1]);
            acc[2][2] = fma2(x45, wk2, acc[2][2]);
            acc[2][3] = fma2(x67, wk2, acc[2][3]);
        }
        #pragma unroll
        for (int rr = 0; rr < 8; rr++) {
            #pragma unroll
            for (int cc = 0; cc < 3; cc++) {
                const int j = lane + 32 * cc;
                if (j < 75) {
                    const float2 v = unpack2(acc[cc][rr >> 1]);
                    sxg[wid][rr][j] = (rr & 1) ? v.y : v.x;
                }
            }
        }
        __syncwarp();

        // ================= consume 8 steps =================
        #pragma unroll
        for (int s = 0; s < 8; s++) {
            const float gir = sxg[wid][s][i];
            const float giz = sxg[wid][s][25 + i];
            const float gin = sxg[wid][s][50 + i];

            const ulonglong2* h4 = (const ulonglong2*)shh[wid][pbuf];
            ULL Ra = 0, Rb = 0, Za = 0, Zb = 0, Na = 0, Nb = 0;
            #pragma unroll
            for (int q = 0; q < 7; q++) {
                const ulonglong2 hv = h4[q];
                Ra = fma2(hv.x, whr[2 * q], Ra);  Rb = fma2(hv.y, whr[2 * q + 1], Rb);
                Za = fma2(hv.x, whz[2 * q], Za);  Zb = fma2(hv.y, whz[2 * q + 1], Zb);
                Na = fma2(hv.x, whn[2 * q], Na);  Nb = fma2(hv.y, whn[2 * q + 1], Nb);
            }
            const float2 ra = unpack2(Ra), rb = unpack2(Rb);
            const float2 za = unpack2(Za), zb = unpack2(Zb);
            const float2 na = unpack2(Na), nb = unpack2(Nb);
            const float ghr = (ra.x + ra.y) + (rb.x + rb.y);
            const float ghz = (za.x + za.y) + (zb.x + zb.y);
            const float ghn = (na.x + na.y) + (nb.x + nb.y);

            const float r  = sig_fast(gir + chr + ghr);
            const float zg = sig_fast(giz + chz + ghz);
            const float n  = tanh_fast(fmaf(r, chn + ghn, gin));
            h = fmaf(zg, h - n, n);

            if (lane < RNN) shh[wid][pbuf ^ 1][lane] = h;
            __syncwarp();
            pbuf ^= 1;
        }
    }

    // stats head: lanes 0..7 -> mu (0..3) / logvar (4..7)
    if (lane < 8) {
        float s = stB[lane];
        #pragma unroll
        for (int k = 0; k < RNN; k++) s = fmaf(shh[wid][pbuf][k], stW[k * 8 + lane], s);
        if (lane < 4) {
            out[Z0_OFF + b * 4 + lane] = s;
            out[MU_OFF + b * 4 + lane] = s;
        } else {
            out[LV_OFF + b * 4 + (lane - 4)] = s;
        }
    }
}

// =====================================================================================
// Kernel 2: dopri5 + FSAL + cubic-Hermite dense output (32 intervals per big step)
// + fused decoder. 4 lanes/element; lane g owns outputs o = g + 4q, q = 0..7.
// =====================================================================================
__device__ __forceinline__ void feval(
    const float (&y)[LAT], float (&k)[LAT],
    const float (&w1)[LAT][5], const float (&b1v)[5],
    const float (&w2)[5][LAT], const float (&b2v)[LAT])
{
    float v[5];
    #pragma unroll
    for (int u = 0; u < 5; u++) {
        float t = b1v[u];
        #pragma unroll
        for (int c = 0; c < LAT; c++) t = fmaf(y[c], w1[c][u], t);
        v[u] = elu_fast(t);
    }
    #pragma unroll
    for (int i = 0; i < LAT; i++) {
        float a  = fmaf(v[0], w2[0][i], v[1] * w2[1][i]);
        float bq = fmaf(v[2], w2[2][i], v[3] * w2[3][i]);
        float s  = fmaf(v[4], w2[4][i], a + bq);
        s += __shfl_xor_sync(0xffffffffu, s, 1);
        s += __shfl_xor_sync(0xffffffffu, s, 2);
        k[i] = s + b2v[i];
    }
}

__device__ __forceinline__ void decode_store(
    const float (&zg)[LAT],
    const float4* __restrict__ sW1, const float2* __restrict__ sW2,
    const float*  __restrict__ sb1, float b20, float b21,
    float* __restrict__ out, int tt, int b)
{
    float x0 = b20, x1 = b21;
    #pragma unroll
    for (int u = 0; u < ODEH; u++) {
        const float4 wv = sW1[u];
        float t = sb1[u];
        t = fmaf(zg[0], wv.x, t);
        t = fmaf(zg[1], wv.y, t);
        t = fmaf(zg[2], wv.z, t);
        t = fmaf(zg[3], wv.w, t);
        t = fmaxf(t, 0.0f);
        const float2 w2v = sW2[u];
        x0 = fmaf(t, w2v.x, x0);
        x1 = fmaf(t, w2v.y, x1);
    }
    float2 ov = {x0, x1};
    *(float2*)(out + XP_OFF + ((size_t)tt * BATCH + b) * 2) = ov;
}

__global__ void __launch_bounds__(128) ode_kernel(
    const float* __restrict__ pt,
    const float* __restrict__ W1,  const float* __restrict__ B1,
    const float* __restrict__ W2,  const float* __restrict__ B2,
    const float* __restrict__ dW1, const float* __restrict__ dB1,
    const float* __restrict__ dW2, const float* __restrict__ dB2,
    float* __restrict__ out)
{
    __shared__ float  spt[NT];
    __shared__ float4 sW1[ODEH];
    __shared__ float2 sW2[ODEH];
    __shared__ float  sb1[ODEH];

    const int tid = threadIdx.x;
    for (int idx = tid; idx < NT; idx += 128) spt[idx] = pt[idx];
    if (tid < ODEH) {
        sW1[tid] = make_float4(dW1[tid], dW1[ODEH + tid], dW1[2 * ODEH + tid], dW1[3 * ODEH + tid]);
        sW2[tid] = make_float2(dW2[tid * 2], dW2[tid * 2 + 1]);
        sb1[tid] = dB1[tid];
    }
    __syncthreads();

    const int gtid = blockIdx.x * 128 + tid;
    const int b    = gtid >> 2;
    const int g    = gtid & 3;
    const float b20 = dB2[0], b21 = dB2[1];

    float w1[LAT][5], b1v[5], w2[5][LAT], b2v[LAT];
    #pragma unroll
    for (int u = 0; u < 5; u++) {
        const int j = g * 5 + u;
        b1v[u] = B1[j];
        #pragma unroll
        for (int c = 0; c < LAT; c++) w1[c][u] = W1[c * ODEH + j];
        #pragma unroll
        for (int i = 0; i < LAT; i++) w2[u][i] = W2[j * LAT + i];
    }
    #pragma unroll
    for (int i = 0; i < LAT; i++) b2v[i] = B2[i];

    const float4 z0v = *(const float4*)(out + Z0_OFF + (size_t)b * 4);
    float z[LAT] = {z0v.x, z0v.y, z0v.z, z0v.w};
    if (g == 0) {
        *(float4*)(out + ZT_OFF + (size_t)b * 4) = z0v;
        decode_store(z, sW1, sW2, sb1, b20, b21, out, 0, b);
    }

    const float A21 = 0.2f;
    const float A31 = 3.0f/40.0f,       A32 = 9.0f/40.0f;
    const float A41 = 44.0f/45.0f,      A42 = -56.0f/15.0f,      A43 = 32.0f/9.0f;
    const float A51 = 19372.0f/6561.0f, A52 = -25360.0f/2187.0f, A53 = 64448.0f/6561.0f, A54 = -212.0f/729.0f;
    const float A61 = 9017.0f/3168.0f,  A62 = -355.0f/33.0f,     A63 = 46732.0f/5247.0f,
                A64 = 49.0f/176.0f,     A65 = -5103.0f/18656.0f;
    const float BB1 = 35.0f/384.0f,     BB3 = 500.0f/1113.0f,    BB4 = 125.0f/192.0f,
                BB5 = -2187.0f/6784.0f, BB6 = 11.0f/84.0f;

    float k1[LAT], k2[LAT], k3[LAT], k4[LAT], k5[LAT], k6[LAT], k7[LAT], y[LAT], z1[LAT];

    feval(z, k1, w1, b1v, w2, b2v);   // initial (FSAL thereafter)

    int m = 0;
    #pragma unroll 1
    for (int grp = 0; grp < 16; ++grp) {
        const int n = (grp < 15) ? 32 : 19;          // 499 = 15*32 + 19
        const float pt0 = spt[m];
        const float h   = spt[m + n] - pt0;

        #pragma unroll
        for (int i = 0; i < LAT; i++) y[i] = fmaf(h, A21 * k1[i], z[i]);
        feval(y, k2, w1, b1v, w2, b2v);
        #pragma unroll
        for (int i = 0; i < LAT; i++) {
            float s = fmaf(A32, k2[i], A31 * k1[i]);
            y[i] = fmaf(h, s, z[i]);
        }
        feval(y, k3, w1, b1v, w2, b2v);
        #pragma unroll
        for (int i = 0; i < LAT; i++) {
            float s = fmaf(A43, k3[i], fmaf(A42, k2[i], A41 * k1[i]));
            y[i] = fmaf(h, s, z[i]);
        }
        feval(y, k4, w1, b1v, w2, b2v);
        #pragma unroll
        for (int i = 0; i < LAT; i++) {
            float s = fmaf(A54, k4[i], fmaf(A53, k3[i], fmaf(A52, k2[i], A51 * k1[i])));
            y[i] = fmaf(h, s, z[i]);
        }
        feval(y, k5, w1, b1v, w2, b2v);
        #pragma unroll
        for (int i = 0; i < LAT; i++) {
            float s = fmaf(A65, k5[i], fmaf(A64, k4[i], fmaf(A63, k3[i], fmaf(A62, k2[i], A61 * k1[i]))));
            y[i] = fmaf(h, s, z[i]);
        }
        feval(y, k6, w1, b1v, w2, b2v);
        #pragma unroll
        for (int i = 0; i < LAT; i++) {
            float s = fmaf(BB6, k6[i], fmaf(BB5, k5[i], fmaf(BB4, k4[i], fmaf(BB3, k3[i], BB1 * k1[i]))));
            z1[i] = fmaf(h, s, z[i]);
        }
        feval(z1, k7, w1, b1v, w2, b2v);  // FSAL: k7 = f(z1) = next k1

        // lane g handles outputs o = g + 4q (o < n); o == n-1 uses exact z1
        #pragma unroll
        for (int q = 0; q < 8; q++) {
            const int o = g + q * 4;
            if (o < n) {
                const int tt = m + 1 + o;
                float zg[LAT];
                if (o == n - 1) {
                    #pragma unroll
                    for (int i = 0; i < LAT; i++) zg[i] = z1[i];
                } else {
                    const float s  = __fdividef(spt[tt] - pt0, h);
                    const float s2 = s * s;
                    const float s3 = s2 * s;
                    const float c0 = 2.0f * s3 - 3.0f * s2 + 1.0f;
                    const float c1 = (s3 - 2.0f * s2 + s) * h;
                    const float c2 = 3.0f * s2 - 2.0f * s3;
                    const float c3 = (s3 - s2) * h;
                    #pragma unroll
                    for (int i = 0; i < LAT; i++)
                        zg[i] = fmaf(c3, k7[i], fmaf(c2, z1[i], fmaf(c1, k1[i], c0 * z[i])));
                }
                float4 zo = {zg[0], zg[1], zg[2], zg[3]};
                *(float4*)(out + ZT_OFF + ((size_t)tt * BATCH + b) * 4) = zo;
                decode_store(zg, sW1, sW2, sb1, b20, b21, out, tt, b);
            }
        }

        #pragma unroll
        for (int i = 0; i < LAT; i++) { z[i] = z1[i]; k1[i] = k7[i]; }
        m += n;
    }
}

// =====================================================================================
extern "C" void kernel_launch(void* const* d_in, const int* in_sizes, int n_in,
                              void* d_out, int out_size)
{
    const float* obs   = (const float*)d_in[0];
    const float* pt    = (const float*)d_in[1];
    const float* encW  = (const float*)d_in[2];
    const float* encB  = (const float*)d_in[3];
    const float* Wih   = (const float*)d_in[4];
    const float* Whh   = (const float*)d_in[5];
    const float* bih   = (const float*)d_in[6];
    const float* bhh   = (const float*)d_in[7];
    const float* stW   = (const float*)d_in[8];
    const float* stB   = (const float*)d_in[9];
    const float* oW1   = (const float*)d_in[10];
    const float* ob1   = (const float*)d_in[11];
    const float* oW2   = (const float*)d_in[12];
    const float* ob2   = (const float*)d_in[13];
    const float* dW1   = (const float*)d_in[14];
    const float* db1   = (const float*)d_in[15];
    const float* dW2   = (const float*)d_in[16];
    const float* db2   = (const float*)d_in[17];
    float* out = (float*)d_out;

    gru_fused_kernel<<<BATCH / 4, 128>>>(obs, encW, encB, Wih, bih, Whh, bhh, stW, stB, out);
    ode_kernel<<<(BATCH * 4) / 128, 128>>>(pt, oW1, ob1, oW2, ob2, dW1, db1, dW2, db2, out);
}

// round 11
// speedup vs baseline: 1.5887x; 1.0400x over previous
#include <cuda_runtime.h>

#define BATCH 4096
#define SEQL  200
#define NT    500
#define OBS   2
#define LAT   4
#define RNN   25
#define ODEH  20

// Output layout: x_pred [T,B,OBS] | z_traj [T,B,LAT] | z0 [B,LAT] | mu [B,LAT] | logvar [B,LAT]
#define XP_OFF 0
#define ZT_OFF (NT * BATCH * OBS)
#define Z0_OFF (ZT_OFF + NT * BATCH * LAT)
#define MU_OFF (Z0_OFF + BATCH * LAT)
#define LV_OFF (MU_OFF + BATCH * LAT)

typedef unsigned long long ULL;

// ---------- f32x2 packed helpers ----------
__device__ __forceinline__ ULL pack2(float lo, float hi) {
    ULL r; asm("mov.b64 %0, {%1, %2};" : "=l"(r) : "f"(lo), "f"(hi)); return r;
}
__device__ __forceinline__ float2 unpack2(ULL v) {
    float2 r; asm("mov.b64 {%0, %1}, %2;" : "=f"(r.x), "=f"(r.y) : "l"(v)); return r;
}
__device__ __forceinline__ ULL fma2(ULL a, ULL b, ULL c) {
    ULL d; asm("fma.rn.f32x2 %0, %1, %2, %3;" : "=l"(d) : "l"(a), "l"(b), "l"(c)); return d;
}

// ---------- fast transcendentals (exp-based, ~1e-6 rel) ----------
__device__ __forceinline__ float sig_fast(float x) {
    return __fdividef(1.0f, 1.0f + __expf(-x));
}
__device__ __forceinline__ float tanh_fast(float x) {
    float ax = fabsf(x);
    float e  = __expf(-2.0f * ax);
    float t  = __fdividef(1.0f - e, 1.0f + e);
    return copysignf(t, x);
}
__device__ __forceinline__ float elu_fast(float x) {
    float m = fminf(x, 0.0f);
    float e = __expf(m) - 1.0f;
    return e + (x - m);
}

// =====================================================================================
// Kernel 1: single-warp fused reverse GRU (round-10 structure, proven). One warp per
// element alternates produce(8-step GI chunk)/consume(8 recurrence steps).
// Change vs round 10: __launch_bounds__(128,3) -> 168-reg budget, no spills in the
// produce loop (peak live regs ~143 exceeded the previous 128 cap).
// =====================================================================================
__global__ void __launch_bounds__(128, 3) gru_fused_kernel(
    const float* __restrict__ obs,
    const float* __restrict__ encW, const float* __restrict__ encB,
    const float* __restrict__ Wih,  const float* __restrict__ bih,
    const float* __restrict__ Whh,  const float* __restrict__ bhh,
    const float* __restrict__ stW,  const float* __restrict__ stB,
    float* __restrict__ out)
{
    __shared__ __align__(16) float sWih[25][76];    // Wih row-major, col 75 = zero pad
    __shared__ __align__(16) float sxp[4][25][12];  // [warp][k][row 0..7 + pad]
    __shared__ __align__(16) float sxg[4][8][76];   // [warp][step-in-chunk][gi column]
    __shared__ __align__(16) float shh[4][2][28];   // [warp][buf][h]

    const int tid  = threadIdx.x;
    const int wid  = tid >> 5;
    const int lane = tid & 31;
    const int b    = blockIdx.x * 4 + wid;
    const int i    = (lane < RNN) ? lane : (RNN - 1);

    // cooperative fill of sWih (uniform across all warps, then one uniform barrier)
    for (int idx = tid; idx < 25 * 76; idx += 128) {
        const int k = idx / 76, j = idx - k * 76;
        sWih[k][j] = (j < 75) ? Wih[k * 75 + j] : 0.f;
    }
    __syncthreads();

    // ---- producer per-lane constants ----
    ULL bias[3];
    #pragma unroll
    for (int c = 0; c < 3; c++) {
        const int j = lane + 32 * c;
        bias[c] = (j < 75) ? pack2(bih[j], bih[j]) : 0ULL;
    }
    const int j2 = (lane + 64 < 75) ? (lane + 64) : 75;     // col 75 is zero pad
    const int kk = (lane < 25) ? lane : 0;
    const float e0 = encW[kk], e1 = encW[25 + kk], eb = encB[kk];
    const float2* ob2 = (const float2*)obs + (size_t)b * SEQL;

    // ---- consumer weights: Whh gate-column i packed over k-pairs (registers) ----
    ULL whr[14], whz[14], whn[14];
    #pragma unroll
    for (int p = 0; p < 14; p++) {
        const int k0 = 2 * p, k1 = k0 + 1;
        const float r0 = (k0 < RNN) ? Whh[k0 * 75 + i]      : 0.f;
        const float r1 = (k1 < RNN) ? Whh[k1 * 75 + i]      : 0.f;
        const float z0 = (k0 < RNN) ? Whh[k0 * 75 + i + 25] : 0.f;
        const float z1 = (k1 < RNN) ? Whh[k1 * 75 + i + 25] : 0.f;
        const float n0 = (k0 < RNN) ? Whh[k0 * 75 + i + 50] : 0.f;
        const float n1 = (k1 < RNN) ? Whh[k1 * 75 + i + 50] : 0.f;
        whr[p] = pack2(r0, r1); whz[p] = pack2(z0, z1); whn[p] = pack2(n0, n1);
    }
    const float chr = bhh[i], chz = bhh[25 + i], chn = bhh[50 + i];

    if (lane < 28) { shh[wid][0][lane] = 0.f; shh[wid][1][lane] = 0.f; }
    __syncwarp();

    float h = 0.f;
    int pbuf = 0;

    #pragma unroll 1
    for (int c = 0; c < 25; c++) {
        // ================= produce chunk c: l = 199-8c-rr, rr = 0..7 =================
        const int l_hi = 199 - 8 * c;
        float2 of2 = make_float2(0.f, 0.f);
        if (lane < 8) of2 = ob2[l_hi - lane];
        #pragma unroll
        for (int rr = 0; rr < 8; rr++) {
            const float o0 = __shfl_sync(0xffffffffu, of2.x, rr);
            const float o1 = __shfl_sync(0xffffffffu, of2.y, rr);
            const float xp = tanh_fast(fmaf(o1, e1, fmaf(o0, e0, eb)));
            if (lane < 25) sxp[wid][lane][rr] = xp;
        }
        __syncwarp();

        ULL acc[3][4];
        #pragma unroll
        for (int cc = 0; cc < 3; cc++)
            #pragma unroll
            for (int pp = 0; pp < 4; pp++) acc[cc][pp] = bias[cc];

        #pragma unroll 5
        for (int k = 0; k < 25; k++) {
            const float4 xa = *(const float4*)&sxp[wid][k][0];   // rows 0..3
            const float4 xb = *(const float4*)&sxp[wid][k][4];   // rows 4..7
            const ULL x01 = pack2(xa.x, xa.y);
            const ULL x23 = pack2(xa.z, xa.w);
            const ULL x45 = pack2(xb.x, xb.y);
            const ULL x67 = pack2(xb.z, xb.w);
            const float w0 = sWih[k][lane];
            const float w1 = sWih[k][lane + 32];
            const float w2 = sWih[k][j2];
            const ULL wk0 = pack2(w0, w0);
            const ULL wk1 = pack2(w1, w1);
            const ULL wk2 = pack2(w2, w2);
            acc[0][0] = fma2(x01, wk0, acc[0][0]);
            acc[0][1] = fma2(x23, wk0, acc[0][1]);
            acc[0][2] = fma2(x45, wk0, acc[0][2]);
            acc[0][3] = fma2(x67, wk0, acc[0][3]);
            acc[1][0] = fma2(x01, wk1, acc[1][0]);
            acc[1][1] = fma2(x23, wk1, acc[1][1]);
            acc[1][2] = fma2(x45, wk1, acc[1][2]);
            acc[1][3] = fma2(x67, wk1, acc[1][3]);
            acc[2][0] = fma2(x01, wk2, acc[2][0]);
            acc[2][1] = fma2(x23, wk2, acc[2][1]);
            acc[2][2] = fma2(x45, wk2, acc[2][2]);
            acc[2][3] = fma2(x67, wk2, acc[2][3]);
        }
        #pragma unroll
        for (int rr = 0; rr < 8; rr++) {
            #pragma unroll
            for (int cc = 0; cc < 3; cc++) {
                const int j = lane + 32 * cc;
                if (j < 75) {
                    const float2 v = unpack2(acc[cc][rr >> 1]);
                    sxg[wid][rr][j] = (rr & 1) ? v.y : v.x;
                }
            }
        }
        __syncwarp();

        // ================= consume 8 steps =================
        #pragma unroll
        for (int s = 0; s < 8; s++) {
            const float gir = sxg[wid][s][i];
            const float giz = sxg[wid][s][25 + i];
            const float gin = sxg[wid][s][50 + i];

            const ulonglong2* h4 = (const ulonglong2*)shh[wid][pbuf];
            ULL Ra = 0, Rb = 0, Za = 0, Zb = 0, Na = 0, Nb = 0;
            #pragma unroll
            for (int q = 0; q < 7; q++) {
                const ulonglong2 hv = h4[q];
                Ra = fma2(hv.x, whr[2 * q], Ra);  Rb = fma2(hv.y, whr[2 * q + 1], Rb);
                Za = fma2(hv.x, whz[2 * q], Za);  Zb = fma2(hv.y, whz[2 * q + 1], Zb);
                Na = fma2(hv.x, whn[2 * q], Na);  Nb = fma2(hv.y, whn[2 * q + 1], Nb);
            }
            const float2 ra = unpack2(Ra), rb = unpack2(Rb);
            const float2 za = unpack2(Za), zb = unpack2(Zb);
            const float2 na = unpack2(Na), nb = unpack2(Nb);
            const float ghr = (ra.x + ra.y) + (rb.x + rb.y);
            const float ghz = (za.x + za.y) + (zb.x + zb.y);
            const float ghn = (na.x + na.y) + (nb.x + nb.y);

            const float r  = sig_fast(gir + chr + ghr);
            const float zg = sig_fast(giz + chz + ghz);
            const float n  = tanh_fast(fmaf(r, chn + ghn, gin));
            h = fmaf(zg, h - n, n);

            if (lane < RNN) shh[wid][pbuf ^ 1][lane] = h;
            __syncwarp();
            pbuf ^= 1;
        }
    }

    // stats head: lanes 0..7 -> mu (0..3) / logvar (4..7)
    if (lane < 8) {
        float s = stB[lane];
        #pragma unroll
        for (int k = 0; k < RNN; k++) s = fmaf(shh[wid][pbuf][k], stW[k * 8 + lane], s);
        if (lane < 4) {
            out[Z0_OFF + b * 4 + lane] = s;
            out[MU_OFF + b * 4 + lane] = s;
        } else {
            out[LV_OFF + b * 4 + (lane - 4)] = s;
        }
    }
}

// =====================================================================================
// Kernel 2: dopri5 + FSAL + cubic-Hermite dense output (64 intervals per big step)
// + fused decoder. 4 lanes/element; lane g owns outputs o = g + 4q, q = 0..15.
// =====================================================================================
__device__ __forceinline__ void feval(
    const float (&y)[LAT], float (&k)[LAT],
    const float (&w1)[LAT][5], const float (&b1v)[5],
    const float (&w2)[5][LAT], const float (&b2v)[LAT])
{
    float v[5];
    #pragma unroll
    for (int u = 0; u < 5; u++) {
        float t = b1v[u];
        #pragma unroll
        for (int c = 0; c < LAT; c++) t = fmaf(y[c], w1[c][u], t);
        v[u] = elu_fast(t);
    }
    #pragma unroll
    for (int i = 0; i < LAT; i++) {
        float a  = fmaf(v[0], w2[0][i], v[1] * w2[1][i]);
        float bq = fmaf(v[2], w2[2][i], v[3] * w2[3][i]);
        float s  = fmaf(v[4], w2[4][i], a + bq);
        s += __shfl_xor_sync(0xffffffffu, s, 1);
        s += __shfl_xor_sync(0xffffffffu, s, 2);
        k[i] = s + b2v[i];
    }
}

__device__ __forceinline__ void decode_store(
    const float (&zg)[LAT],
    const float4* __restrict__ sW1, const float2* __restrict__ sW2,
    const float*  __restrict__ sb1, float b20, float b21,
    float* __restrict__ out, int tt, int b)
{
    float x0 = b20, x1 = b21;
    #pragma unroll
    for (int u = 0; u < ODEH; u++) {
        const float4 wv = sW1[u];
        float t = sb1[u];
        t = fmaf(zg[0], wv.x, t);
        t = fmaf(zg[1], wv.y, t);
        t = fmaf(zg[2], wv.z, t);
        t = fmaf(zg[3], wv.w, t);
        t = fmaxf(t, 0.0f);
        const float2 w2v = sW2[u];
        x0 = fmaf(t, w2v.x, x0);
        x1 = fmaf(t, w2v.y, x1);
    }
    float2 ov = {x0, x1};
    *(float2*)(out + XP_OFF + ((size_t)tt * BATCH + b) * 2) = ov;
}

__global__ void __launch_bounds__(128) ode_kernel(
    const float* __restrict__ pt,
    const float* __restrict__ W1,  const float* __restrict__ B1,
    const float* __restrict__ W2,  const float* __restrict__ B2,
    const float* __restrict__ dW1, const float* __restrict__ dB1,
    const float* __restrict__ dW2, const float* __restrict__ dB2,
    float* __restrict__ out)
{
    __shared__ float  spt[NT];
    __shared__ float4 sW1[ODEH];
    __shared__ float2 sW2[ODEH];
    __shared__ float  sb1[ODEH];

    const int tid = threadIdx.x;
    for (int idx = tid; idx < NT; idx += 128) spt[idx] = pt[idx];
    if (tid < ODEH) {
        sW1[tid] = make_float4(dW1[tid], dW1[ODEH + tid], dW1[2 * ODEH + tid], dW1[3 * ODEH + tid]);
        sW2[tid] = make_float2(dW2[tid * 2], dW2[tid * 2 + 1]);
        sb1[tid] = dB1[tid];
    }
    __syncthreads();

    const int gtid = blockIdx.x * 128 + tid;
    const int b    = gtid >> 2;
    const int g    = gtid & 3;
    const float b20 = dB2[0], b21 = dB2[1];

    float w1[LAT][5], b1v[5], w2[5][LAT], b2v[LAT];
    #pragma unroll
    for (int u = 0; u < 5; u++) {
        const int j = g * 5 + u;
        b1v[u] = B1[j];
        #pragma unroll
        for (int c = 0; c < LAT; c++) w1[c][u] = W1[c * ODEH + j];
        #pragma unroll
        for (int i = 0; i < LAT; i++) w2[u][i] = W2[j * LAT + i];
    }
    #pragma unroll
    for (int i = 0; i < LAT; i++) b2v[i] = B2[i];

    const float4 z0v = *(const float4*)(out + Z0_OFF + (size_t)b * 4);
    float z[LAT] = {z0v.x, z0v.y, z0v.z, z0v.w};
    if (g == 0) {
        *(float4*)(out + ZT_OFF + (size_t)b * 4) = z0v;
        decode_store(z, sW1, sW2, sb1, b20, b21, out, 0, b);
    }

    const float A21 = 0.2f;
    const float A31 = 3.0f/40.0f,       A32 = 9.0f/40.0f;
    const float A41 = 44.0f/45.0f,      A42 = -56.0f/15.0f,      A43 = 32.0f/9.0f;
    const float A51 = 19372.0f/6561.0f, A52 = -25360.0f/2187.0f, A53 = 64448.0f/6561.0f, A54 = -212.0f/729.0f;
    const float A61 = 9017.0f/3168.0f,  A62 = -355.0f/33.0f,     A63 = 46732.0f/5247.0f,
                A64 = 49.0f/176.0f,     A65 = -5103.0f/18656.0f;
    const float BB1 = 35.0f/384.0f,     BB3 = 500.0f/1113.0f,    BB4 = 125.0f/192.0f,
                BB5 = -2187.0f/6784.0f, BB6 = 11.0f/84.0f;

    float k1[LAT], k2[LAT], k3[LAT], k4[LAT], k5[LAT], k6[LAT], k7[LAT], y[LAT], z1[LAT];

    feval(z, k1, w1, b1v, w2, b2v);   // initial (FSAL thereafter)

    int m = 0;
    #pragma unroll 1
    for (int grp = 0; grp < 8; ++grp) {
        const int n = (grp < 7) ? 64 : 51;           // 499 = 7*64 + 51
        const float pt0 = spt[m];
        const float h   = spt[m + n] - pt0;

        #pragma unroll
        for (int i = 0; i < LAT; i++) y[i] = fmaf(h, A21 * k1[i], z[i]);
        feval(y, k2, w1, b1v, w2, b2v);
        #pragma unroll
        for (int i = 0; i < LAT; i++) {
            float s = fmaf(A32, k2[i], A31 * k1[i]);
            y[i] = fmaf(h, s, z[i]);
        }
        feval(y, k3, w1, b1v, w2, b2v);
        #pragma unroll
        for (int i = 0; i < LAT; i++) {
            float s = fmaf(A43, k3[i], fmaf(A42, k2[i], A41 * k1[i]));
            y[i] = fmaf(h, s, z[i]);
        }
        feval(y, k4, w1, b1v, w2, b2v);
        #pragma unroll
        for (int i = 0; i < LAT; i++) {
            float s = fmaf(A54, k4[i], fmaf(A53, k3[i], fmaf(A52, k2[i], A51 * k1[i])));
            y[i] = fmaf(h, s, z[i]);
        }
        feval(y, k5, w1, b1v, w2, b2v);
        #pragma unroll
        for (int i = 0; i < LAT; i++) {
            float s = fmaf(A65, k5[i], fmaf(A64, k4[i], fmaf(A63, k3[i], fmaf(A62, k2[i], A61 * k1[i]))));
            y[i] = fmaf(h, s, z[i]);
        }
        feval(y, k6, w1, b1v, w2, b2v);
        #pragma unroll
        for (int i = 0; i < LAT; i++) {
            float s = fmaf(BB6, k6[i], fmaf(BB5, k5[i], fmaf(BB4, k4[i], fmaf(BB3, k3[i], BB1 * k1[i]))));
            z1[i] = fmaf(h, s, z[i]);
        }
        feval(z1, k7, w1, b1v, w2, b2v);  // FSAL: k7 = f(z1) = next k1

        // lane g handles outputs o = g + 4q (o < n); o == n-1 uses exact z1
        #pragma unroll 1
        for (int q = 0; q < 16; q++) {
            const int o = g + q * 4;
            if (o < n) {
                const int tt = m + 1 + o;
                float zg[LAT];
                if (o == n - 1) {
                    #pragma unroll
                    for (int i = 0; i < LAT; i++) zg[i] = z1[i];
                } else {
                    const float s  = __fdividef(spt[tt] - pt0, h);
                    const float s2 = s * s;
                    const float s3 = s2 * s;
                    const float c0 = 2.0f * s3 - 3.0f * s2 + 1.0f;
                    const float c1 = (s3 - 2.0f * s2 + s) * h;
                    const float c2 = 3.0f * s2 - 2.0f * s3;
                    const float c3 = (s3 - s2) * h;
                    #pragma unroll
                    for (int i = 0; i < LAT; i++)
                        zg[i] = fmaf(c3, k7[i], fmaf(c2, z1[i], fmaf(c1, k1[i], c0 * z[i])));
                }
                float4 zo = {zg[0], zg[1], zg[2], zg[3]};
                *(float4*)(out + ZT_OFF + ((size_t)tt * BATCH + b) * 4) = zo;
                decode_store(zg, sW1, sW2, sb1, b20, b21, out, tt, b);
            }
        }

        #pragma unroll
        for (int i = 0; i < LAT; i++) { z[i] = z1[i]; k1[i] = k7[i]; }
        m += n;
    }
}

// =====================================================================================
extern "C" void kernel_launch(void* const* d_in, const int* in_sizes, int n_in,
                              void* d_out, int out_size)
{
    const float* obs   = (const float*)d_in[0];
    const float* pt    = (const float*)d_in[1];
    const float* encW  = (const float*)d_in[2];
    const float* encB  = (const float*)d_in[3];
    const float* Wih   = (const float*)d_in[4];
    const float* Whh   = (const float*)d_in[5];
    const float* bih   = (const float*)d_in[6];
    const float* bhh   = (const float*)d_in[7];
    const float* stW   = (const float*)d_in[8];
    const float* stB   = (const float*)d_in[9];
    const float* oW1   = (const float*)d_in[10];
    const float* ob1   = (const float*)d_in[11];
    const float* oW2   = (const float*)d_in[12];
    const float* ob2   = (const float*)d_in[13];
    const float* dW1   = (const float*)d_in[14];
    const float* db1   = (const float*)d_in[15];
    const float* dW2   = (const float*)d_in[16];
    const float* db2   = (const float*)d_in[17];
    float* out = (float*)d_out;

    gru_fused_kernel<<<BATCH / 4, 128>>>(obs, encW, encB, Wih, bih, Whh, bhh, stW, stB, out);
    ode_kernel<<<(BATCH * 4) / 128, 128>>>(pt, oW1, ob1, oW2, ob2, dW1, db1, dW2, db2, out);
}